// round 5
// baseline (speedup 1.0000x reference)
#include <cuda_runtime.h>
#include <cfloat>
#include <cstdint>

#define Bz 4
#define NN0 8192
#define NN1 2048
#define NN2 512
#define NN3 128

typedef unsigned long long u64;

__device__ __forceinline__ u64 pack2(float x, float y) {
    u64 r; asm("mov.b64 %0, {%1, %2};" : "=l"(r) : "f"(x), "f"(y)); return r;
}
__device__ __forceinline__ float2 unpack2(u64 v) {
    float2 r; asm("mov.b64 {%0, %1}, %2;" : "=f"(r.x), "=f"(r.y) : "l"(v)); return r;
}
__device__ __forceinline__ u64 ffma2(u64 a, u64 b, u64 c) {
    u64 d; asm("fma.rn.f32x2 %0, %1, %2, %3;" : "=l"(d) : "l"(a), "l"(b), "l"(c)); return d;
}
__device__ __forceinline__ unsigned ordf(float f) {
    unsigned b = __float_as_uint(f);
    return b ^ (((unsigned)((int)b >> 31)) | 0x80000000u);
}
__device__ __forceinline__ float unordf(unsigned m) {
    unsigned b = m ^ ((m & 0x80000000u) ? 0x80000000u : 0xffffffffu);
    return __uint_as_float(b);
}

// ---------------- scratch (allocation-free) ----------------
__device__ int   g_idx0[Bz*NN1*16];
__device__ int   g_idx1[Bz*NN2*16];
__device__ int   g_idx2[Bz*NN3*16];
__device__ int   g_uidx0[Bz*NN2*3];
__device__ float g_ud20 [Bz*NN2*3];
__device__ int   g_uidx1[Bz*NN1*3];
__device__ float g_ud21 [Bz*NN1*3];
__device__ int   g_uidx2[Bz*NN0*3];
__device__ float g_ud22 [Bz*NN0*3];
__device__ float g_x1 [Bz*NN1*128];
__device__ float g_x2 [Bz*NN2*256];
__device__ float g_x3 [Bz*NN3*512];
__device__ float g_up0[Bz*NN2*256];
__device__ float g_up1[Bz*NN1*128];
__device__ __align__(16) float g_wdup[2*806656];

#define OFF_D0W1 0
#define OFF_D0W2 768
#define OFF_D1W1 17152
#define OFF_D1W2 50688
#define OFF_D2W1 116224
#define OFF_D2W2 248832
#define OFF_U0W  510976
#define OFF_U1W  707584
#define OFF_U2W  756736
#define OFF_FW1  773888
#define OFF_FW2  790272
#define W_TOTAL  806656

// ---------------- weight duplication prep ----------------
__global__ void dup_weights_kernel(const float* __restrict__ s0, const float* __restrict__ s1,
                                   const float* __restrict__ s2, const float* __restrict__ s3,
                                   const float* __restrict__ s4, const float* __restrict__ s5,
                                   const float* __restrict__ s6, const float* __restrict__ s7,
                                   const float* __restrict__ s8, const float* __restrict__ s9,
                                   const float* __restrict__ s10, float* __restrict__ dst) {
    int gid = blockIdx.x*256 + threadIdx.x;
    if (gid >= W_TOTAL) return;
    const int offs[11] = {OFF_D0W1,OFF_D0W2,OFF_D1W1,OFF_D1W2,OFF_D2W1,OFF_D2W2,
                          OFF_U0W,OFF_U1W,OFF_U2W,OFF_FW1,OFF_FW2};
    const float* srcs[11] = {s0,s1,s2,s3,s4,s5,s6,s7,s8,s9,s10};
    int seg = 0;
    #pragma unroll
    for (int i = 1; i < 11; i++) seg = (gid >= offs[i]) ? i : seg;
    float v = srcs[seg][gid - offs[seg]];
    reinterpret_cast<float2*>(dst)[gid] = make_float2(v, v);
}

// ---------------- KNN K=16: NWARP warps local-top16 + single-warp merge ----------------
template<int CNT, int NWARP>
__global__ void knn16_kernel(const float* __restrict__ qpos, const float* __restrict__ rpos,
                             int Nq, int* __restrict__ oidx) {
    __shared__ u64 skey[NWARP*16];
    int b = blockIdx.y, q = blockIdx.x;
    int lane = threadIdx.x & 31, w = threadIdx.x >> 5;
    const float* qp = qpos + ((size_t)b*NN0 + q)*3;
    float qx = qp[0], qy = qp[1], qz = qp[2];
    float qq = qx*qx + qy*qy + qz*qz;
    const float* rp = rpos + (size_t)b*NN0*3;
    int base = w*CNT*32;

    unsigned ud[CNT];
    unsigned lmin = 0xffffffffu; int lslot = 0;
    #pragma unroll
    for (int i = 0; i < CNT; i++) {
        int r = base + i*32 + lane;
        float rx = rp[3*r+0], ry = rp[3*r+1], rz = rp[3*r+2];
        float rr = rx*rx + ry*ry + rz*rz;
        float dt = qx*rx + qy*ry + qz*rz;
        unsigned u = ordf(qq + rr - 2.0f*dt);
        ud[i] = u;
        if (u < lmin) { lmin = u; lslot = i; }
    }
    // local top-16 extraction (ascending); all writes static-indexed (regs stay regs)
    for (int s = 0; s < 16; s++) {
        unsigned gmin = __reduce_min_sync(0xffffffffu, lmin);
        unsigned cand = (lmin == gmin) ? (unsigned)(lslot*32 + lane) : 0xffffffffu;
        unsigned rloc = __reduce_min_sync(0xffffffffu, cand);
        if (lane == 0) skey[w*16 + s] = ((u64)gmin << 32) | (unsigned)(base + rloc);
        if ((rloc & 31) == (unsigned)lane) {
            int slot = (int)(rloc >> 5);
            #pragma unroll
            for (int i = 0; i < CNT; i++) if (i == slot) ud[i] = 0xffffffffu;
            unsigned nm = 0xffffffffu; int ns = 0;
            #pragma unroll
            for (int i = 0; i < CNT; i++) if (ud[i] < nm) { nm = ud[i]; ns = i; }
            lmin = nm; lslot = ns;
        }
    }
    __syncthreads();
    // warp 0: NWARP-way merge of sorted 16-lists
    if (w == 0) {
        u64 head = ~0ull; int ptr = 0;
        if (lane < NWARP) head = skey[lane*16];
        size_t obase = ((size_t)b*Nq + q)*16;
        for (int s = 0; s < 16; s++) {
            unsigned hi = (unsigned)(head >> 32);
            unsigned mh = __reduce_min_sync(0xffffffffu, hi);
            unsigned lo = (hi == mh) ? (unsigned)head : 0xffffffffu;
            unsigned ml = __reduce_min_sync(0xffffffffu, lo);
            if (lane == 0) oidx[obase + s] = (int)ml;
            u64 best = ((u64)mh << 32) | ml;
            if (head == best) {
                ptr++;
                head = (ptr < 16) ? skey[lane*16 + ptr] : ~0ull;
            }
        }
    }
}

// ---------------- KNN K=3, block variant (for large Nr): local top-3 + merge ----------------
template<int CNT, int NWARP>
__global__ void knn3b_kernel(const float* __restrict__ qpos, const float* __restrict__ rpos,
                             int Nq, int* __restrict__ oidx, float* __restrict__ od2) {
    __shared__ u64 skey[NWARP*3];
    int b = blockIdx.y, q = blockIdx.x;
    int lane = threadIdx.x & 31, w = threadIdx.x >> 5;
    const float* qp = qpos + ((size_t)b*NN0 + q)*3;
    float qx = qp[0], qy = qp[1], qz = qp[2];
    float qq = qx*qx + qy*qy + qz*qz;
    const float* rp = rpos + (size_t)b*NN0*3;
    int base = w*CNT*32;

    unsigned ud[CNT];
    unsigned lmin = 0xffffffffu; int lslot = 0;
    #pragma unroll
    for (int i = 0; i < CNT; i++) {
        int r = base + i*32 + lane;
        float rx = rp[3*r+0], ry = rp[3*r+1], rz = rp[3*r+2];
        float rr = rx*rx + ry*ry + rz*rz;
        float dt = qx*rx + qy*ry + qz*rz;
        unsigned u = ordf(qq + rr - 2.0f*dt);
        ud[i] = u;
        if (u < lmin) { lmin = u; lslot = i; }
    }
    #pragma unroll
    for (int s = 0; s < 3; s++) {
        unsigned gmin = __reduce_min_sync(0xffffffffu, lmin);
        unsigned cand = (lmin == gmin) ? (unsigned)(lslot*32 + lane) : 0xffffffffu;
        unsigned rloc = __reduce_min_sync(0xffffffffu, cand);
        if (lane == 0) skey[w*3 + s] = ((u64)gmin << 32) | (unsigned)(base + rloc);
        if (s < 2 && (rloc & 31) == (unsigned)lane) {
            int slot = (int)(rloc >> 5);
            #pragma unroll
            for (int i = 0; i < CNT; i++) if (i == slot) ud[i] = 0xffffffffu;
            unsigned nm = 0xffffffffu; int ns = 0;
            #pragma unroll
            for (int i = 0; i < CNT; i++) if (ud[i] < nm) { nm = ud[i]; ns = i; }
            lmin = nm; lslot = ns;
        }
    }
    __syncthreads();
    if (w == 0) {
        u64 head = ~0ull; int ptr = 0;
        if (lane < NWARP) head = skey[lane*3];
        size_t obase = ((size_t)b*Nq + q)*3;
        #pragma unroll
        for (int s = 0; s < 3; s++) {
            unsigned hi = (unsigned)(head >> 32);
            unsigned mh = __reduce_min_sync(0xffffffffu, hi);
            unsigned lo = (hi == mh) ? (unsigned)head : 0xffffffffu;
            unsigned ml = __reduce_min_sync(0xffffffffu, lo);
            if (lane == 0) {
                oidx[obase + s] = (int)ml;
                od2[obase + s]  = fmaxf(unordf(mh), 0.0f);
            }
            u64 best = ((u64)mh << 32) | ml;
            if (head == best) {
                ptr++;
                head = (ptr < 3) ? skey[lane*3 + ptr] : ~0ull;
            }
        }
    }
}

// ---------------- KNN K=3, warp variant (small Nr): one warp per query ----------------
template<int CNT>
__global__ void knn3_kernel(const float* __restrict__ qpos, const float* __restrict__ rpos,
                            int Nq, int* __restrict__ oidx, float* __restrict__ od2) {
    int b = blockIdx.y;
    int lane = threadIdx.x & 31;
    int q = blockIdx.x*8 + (threadIdx.x >> 5);
    const float* qp = qpos + ((size_t)b*NN0 + q)*3;
    float qx = qp[0], qy = qp[1], qz = qp[2];
    float qq = qx*qx + qy*qy + qz*qz;
    const float* rp = rpos + (size_t)b*NN0*3;

    unsigned ud[CNT];
    unsigned lmin = 0xffffffffu; int lslot = 0;
    #pragma unroll
    for (int i = 0; i < CNT; i++) {
        int r = i*32 + lane;
        float rx = rp[3*r+0], ry = rp[3*r+1], rz = rp[3*r+2];
        float rr = rx*rx + ry*ry + rz*rz;
        float dt = qx*rx + qy*ry + qz*rz;
        unsigned u = ordf(qq + rr - 2.0f*dt);
        ud[i] = u;
        if (u < lmin) { lmin = u; lslot = i; }
    }
    size_t obase = ((size_t)b*Nq + q)*3;
    #pragma unroll
    for (int s = 0; s < 3; s++) {
        unsigned gmin = __reduce_min_sync(0xffffffffu, lmin);
        unsigned cand = (lmin == gmin) ? (unsigned)(lslot*32 + lane) : 0xffffffffu;
        unsigned rwin = __reduce_min_sync(0xffffffffu, cand);
        if (lane == 0) {
            oidx[obase + s] = (int)rwin;
            od2[obase + s]  = fmaxf(unordf(gmin), 0.0f);
        }
        if (s < 2 && (rwin & 31) == (unsigned)lane) {
            int slot = (int)(rwin >> 5);
            #pragma unroll
            for (int i = 0; i < CNT; i++) if (i == slot) ud[i] = 0xffffffffu;
            unsigned nm = 0xffffffffu; int ns = 0;
            #pragma unroll
            for (int i = 0; i < CNT; i++) if (ud[i] < nm) { nm = ud[i]; ns = i; }
            lmin = nm; lslot = ns;
        }
    }
}

// ---------------- down0: CIN=6 -> 128 -> 128, 2 centers per block ----------------
__global__ void down0_kernel(const float* __restrict__ xprev, const float* __restrict__ pos,
                             const int* __restrict__ idx,
                             const float* __restrict__ W1d, const float* __restrict__ b1,
                             const float* __restrict__ W2d, const float* __restrict__ b2,
                             float* __restrict__ xout) {
    __shared__ float featT[2][6*16];
    __shared__ float hT[2][128*16];
    __shared__ int nbs[2][16];
    int b = blockIdx.y;
    int h = threadIdx.x >> 6, t = threadIdx.x & 63;
    int q = blockIdx.x*2 + h;
    if (t < 16) nbs[h][t] = idx[((size_t)b*NN1 + q)*16 + t];
    __syncthreads();
    const float* rp = pos + (size_t)b*NN0*3;
    float cx = rp[3*q+0], cy = rp[3*q+1], cz = rp[3*q+2];
    const float* xp = xprev + (size_t)b*NN0*3;
    for (int e = t; e < 96; e += 64) {
        int d = e >> 4, k = e & 15;
        int nb = nbs[h][k];
        float v;
        if      (d == 0) v = rp[3*nb+0] - cx;
        else if (d == 1) v = rp[3*nb+1] - cy;
        else if (d == 2) v = rp[3*nb+2] - cz;
        else             v = xp[3*nb + (d-3)];
        featT[h][d*16 + k] = v;
    }
    __syncthreads();
    int j0 = 2*t;
    u64 a0[8], a1[8];
    {
        float2 bb = *reinterpret_cast<const float2*>(&b1[j0]);
        u64 p0 = pack2(bb.x, bb.x), p1 = pack2(bb.y, bb.y);
        #pragma unroll
        for (int i = 0; i < 8; i++) { a0[i] = p0; a1[i] = p1; }
    }
    #pragma unroll
    for (int d = 0; d < 6; d++) {
        ulonglong2 ww = *reinterpret_cast<const ulonglong2*>(W1d + 2*(d*128 + j0));
        const ulonglong2* f = reinterpret_cast<const ulonglong2*>(featT[h] + d*16);
        ulonglong2 f0 = f[0], f1 = f[1], f2 = f[2], f3 = f[3];
        a0[0]=ffma2(f0.x,ww.x,a0[0]); a0[1]=ffma2(f0.y,ww.x,a0[1]);
        a0[2]=ffma2(f1.x,ww.x,a0[2]); a0[3]=ffma2(f1.y,ww.x,a0[3]);
        a0[4]=ffma2(f2.x,ww.x,a0[4]); a0[5]=ffma2(f2.y,ww.x,a0[5]);
        a0[6]=ffma2(f3.x,ww.x,a0[6]); a0[7]=ffma2(f3.y,ww.x,a0[7]);
        a1[0]=ffma2(f0.x,ww.y,a1[0]); a1[1]=ffma2(f0.y,ww.y,a1[1]);
        a1[2]=ffma2(f1.x,ww.y,a1[2]); a1[3]=ffma2(f1.y,ww.y,a1[3]);
        a1[4]=ffma2(f2.x,ww.y,a1[4]); a1[5]=ffma2(f2.y,ww.y,a1[5]);
        a1[6]=ffma2(f3.x,ww.y,a1[6]); a1[7]=ffma2(f3.y,ww.y,a1[7]);
    }
    {
        float4* h0 = reinterpret_cast<float4*>(hT[h] + (size_t)j0*16);
        float4* h1 = reinterpret_cast<float4*>(hT[h] + (size_t)(j0+1)*16);
        #pragma unroll
        for (int i = 0; i < 4; i++) {
            float2 x0 = unpack2(a0[2*i]), x1 = unpack2(a0[2*i+1]);
            h0[i] = make_float4(fmaxf(x0.x,0.f), fmaxf(x0.y,0.f), fmaxf(x1.x,0.f), fmaxf(x1.y,0.f));
            float2 y0 = unpack2(a1[2*i]), y1 = unpack2(a1[2*i+1]);
            h1[i] = make_float4(fmaxf(y0.x,0.f), fmaxf(y0.y,0.f), fmaxf(y1.x,0.f), fmaxf(y1.y,0.f));
        }
    }
    __syncthreads();
    {
        float2 bb = *reinterpret_cast<const float2*>(&b2[j0]);
        u64 p0 = pack2(bb.x, bb.x), p1 = pack2(bb.y, bb.y);
        #pragma unroll
        for (int i = 0; i < 8; i++) { a0[i] = p0; a1[i] = p1; }
    }
    #pragma unroll 2
    for (int d = 0; d < 128; d++) {
        ulonglong2 ww = *reinterpret_cast<const ulonglong2*>(W2d + 2*(d*128 + j0));
        const ulonglong2* f = reinterpret_cast<const ulonglong2*>(hT[h] + d*16);
        ulonglong2 f0 = f[0], f1 = f[1], f2 = f[2], f3 = f[3];
        a0[0]=ffma2(f0.x,ww.x,a0[0]); a0[1]=ffma2(f0.y,ww.x,a0[1]);
        a0[2]=ffma2(f1.x,ww.x,a0[2]); a0[3]=ffma2(f1.y,ww.x,a0[3]);
        a0[4]=ffma2(f2.x,ww.x,a0[4]); a0[5]=ffma2(f2.y,ww.x,a0[5]);
        a0[6]=ffma2(f3.x,ww.x,a0[6]); a0[7]=ffma2(f3.y,ww.x,a0[7]);
        a1[0]=ffma2(f0.x,ww.y,a1[0]); a1[1]=ffma2(f0.y,ww.y,a1[1]);
        a1[2]=ffma2(f1.x,ww.y,a1[2]); a1[3]=ffma2(f1.y,ww.y,a1[3]);
        a1[4]=ffma2(f2.x,ww.y,a1[4]); a1[5]=ffma2(f2.y,ww.y,a1[5]);
        a1[6]=ffma2(f3.x,ww.y,a1[6]); a1[7]=ffma2(f3.y,ww.y,a1[7]);
    }
    float m0 = -FLT_MAX, m1 = -FLT_MAX;
    #pragma unroll
    for (int i = 0; i < 8; i++) {
        float2 x = unpack2(a0[i]); m0 = fmaxf(m0, fmaxf(x.x, x.y));
        float2 y = unpack2(a1[i]); m1 = fmaxf(m1, fmaxf(y.x, y.y));
    }
    *reinterpret_cast<float2*>(&xout[((size_t)b*NN1 + q)*128 + j0]) = make_float2(m0, m1);
}

// ---------------- down (j-block=4): gather + 2-layer MLP + max over 16 ----------------
template<int C_PREV, int C_HID>
__global__ void down4_kernel(const float* __restrict__ xprev, const float* __restrict__ pos,
                             const int* __restrict__ idx,
                             const float* __restrict__ W1d, const float* __restrict__ b1,
                             const float* __restrict__ W2d, const float* __restrict__ b2,
                             float* __restrict__ xout, int Nq, int xbs) {
    constexpr int CIN = 3 + C_PREV;
    extern __shared__ float sm[];
    float* featT = sm;               // CIN*16
    float* hT    = sm + CIN*16;      // C_HID*16
    __shared__ int nbs[16];
    int b = blockIdx.y, q = blockIdx.x;
    if (threadIdx.x < 16) nbs[threadIdx.x] = idx[((size_t)b*Nq + q)*16 + threadIdx.x];
    __syncthreads();
    const float* rp = pos + (size_t)b*NN0*3;
    float cx = rp[3*q+0], cy = rp[3*q+1], cz = rp[3*q+2];
    const float* xp = xprev + (size_t)b*xbs;
    for (int e = threadIdx.x; e < 16*CIN; e += blockDim.x) {
        int d = e >> 4, k = e & 15;
        int nb = nbs[k];
        float v;
        if      (d == 0) v = rp[3*nb+0] - cx;
        else if (d == 1) v = rp[3*nb+1] - cy;
        else if (d == 2) v = rp[3*nb+2] - cz;
        else             v = xp[(size_t)nb*C_PREV + (d-3)];
        featT[d*16 + k] = v;
    }
    __syncthreads();
    int j0 = 4*threadIdx.x;
    u64 A[4][8];
    {
        float4 bb = *reinterpret_cast<const float4*>(&b1[j0]);
        float bc[4] = {bb.x, bb.y, bb.z, bb.w};
        #pragma unroll
        for (int c = 0; c < 4; c++) {
            u64 p = pack2(bc[c], bc[c]);
            #pragma unroll
            for (int i = 0; i < 8; i++) A[c][i] = p;
        }
    }
    for (int d = 0; d < CIN; d++) {
        const ulonglong2* wp = reinterpret_cast<const ulonglong2*>(W1d + 2*(d*C_HID + j0));
        ulonglong2 wa = wp[0], wb = wp[1];
        u64 w4[4] = {wa.x, wa.y, wb.x, wb.y};
        const ulonglong2* f = reinterpret_cast<const ulonglong2*>(featT + d*16);
        ulonglong2 f0 = f[0], f1 = f[1], f2 = f[2], f3 = f[3];
        #pragma unroll
        for (int c = 0; c < 4; c++) {
            A[c][0]=ffma2(f0.x,w4[c],A[c][0]); A[c][1]=ffma2(f0.y,w4[c],A[c][1]);
            A[c][2]=ffma2(f1.x,w4[c],A[c][2]); A[c][3]=ffma2(f1.y,w4[c],A[c][3]);
            A[c][4]=ffma2(f2.x,w4[c],A[c][4]); A[c][5]=ffma2(f2.y,w4[c],A[c][5]);
            A[c][6]=ffma2(f3.x,w4[c],A[c][6]); A[c][7]=ffma2(f3.y,w4[c],A[c][7]);
        }
    }
    #pragma unroll
    for (int c = 0; c < 4; c++) {
        float4* hr = reinterpret_cast<float4*>(hT + (size_t)(j0+c)*16);
        #pragma unroll
        for (int i = 0; i < 4; i++) {
            float2 x0 = unpack2(A[c][2*i]), x1 = unpack2(A[c][2*i+1]);
            hr[i] = make_float4(fmaxf(x0.x,0.f), fmaxf(x0.y,0.f), fmaxf(x1.x,0.f), fmaxf(x1.y,0.f));
        }
    }
    __syncthreads();
    {
        float4 bb = *reinterpret_cast<const float4*>(&b2[j0]);
        float bc[4] = {bb.x, bb.y, bb.z, bb.w};
        #pragma unroll
        for (int c = 0; c < 4; c++) {
            u64 p = pack2(bc[c], bc[c]);
            #pragma unroll
            for (int i = 0; i < 8; i++) A[c][i] = p;
        }
    }
    for (int d = 0; d < C_HID; d++) {
        const ulonglong2* wp = reinterpret_cast<const ulonglong2*>(W2d + 2*(d*C_HID + j0));
        ulonglong2 wa = wp[0], wb = wp[1];
        u64 w4[4] = {wa.x, wa.y, wb.x, wb.y};
        const ulonglong2* f = reinterpret_cast<const ulonglong2*>(hT + d*16);
        ulonglong2 f0 = f[0], f1 = f[1], f2 = f[2], f3 = f[3];
        #pragma unroll
        for (int c = 0; c < 4; c++) {
            A[c][0]=ffma2(f0.x,w4[c],A[c][0]); A[c][1]=ffma2(f0.y,w4[c],A[c][1]);
            A[c][2]=ffma2(f1.x,w4[c],A[c][2]); A[c][3]=ffma2(f1.y,w4[c],A[c][3]);
            A[c][4]=ffma2(f2.x,w4[c],A[c][4]); A[c][5]=ffma2(f2.y,w4[c],A[c][5]);
            A[c][6]=ffma2(f3.x,w4[c],A[c][6]); A[c][7]=ffma2(f3.y,w4[c],A[c][7]);
        }
    }
    float m[4];
    #pragma unroll
    for (int c = 0; c < 4; c++) {
        float mm = -FLT_MAX;
        #pragma unroll
        for (int i = 0; i < 8; i++) {
            float2 x = unpack2(A[c][i]); mm = fmaxf(mm, fmaxf(x.x, x.y));
        }
        m[c] = mm;
    }
    *reinterpret_cast<float4*>(&xout[((size_t)b*Nq + q)*C_HID + j0]) =
        make_float4(m[0], m[1], m[2], m[3]);
}

// ---------------- up: 3-NN inverse-distance interp + cat + linear + relu ----------------
template<int C_XC, int C_PRV, int C_OUT>
__global__ void up_kernel(const float* __restrict__ xc, const float* __restrict__ prv,
                          const int* __restrict__ idx, const float* __restrict__ d2,
                          const float* __restrict__ Wd, const float* __restrict__ bias,
                          float* __restrict__ out, int Nq, int Nc) {
    constexpr int CIN = C_XC + C_PRV;
    constexpr int QT = 16;
    extern __shared__ float sm[];
    float* featT = sm;               // CIN * 16, [d][q]
    __shared__ float wsh[QT][3];
    __shared__ int   ish[QT][3];
    int b = blockIdx.y;
    int q0 = blockIdx.x * QT;
    if (threadIdx.x < QT) {
        int q = q0 + threadIdx.x;
        size_t base = ((size_t)b*Nq + q)*3;
        float w0 = 1.0f/(d2[base+0] + 1e-8f);
        float w1 = 1.0f/(d2[base+1] + 1e-8f);
        float w2 = 1.0f/(d2[base+2] + 1e-8f);
        float s = w0 + w1 + w2;
        wsh[threadIdx.x][0] = w0/s; wsh[threadIdx.x][1] = w1/s; wsh[threadIdx.x][2] = w2/s;
        ish[threadIdx.x][0] = idx[base+0]; ish[threadIdx.x][1] = idx[base+1]; ish[threadIdx.x][2] = idx[base+2];
    }
    __syncthreads();
    const float* xcb = xc + (size_t)b*Nc*C_XC;
    for (int e = threadIdx.x; e < CIN*QT; e += blockDim.x) {
        int d = e >> 4, qq = e & 15;
        float v;
        if (d < C_XC) {
            v = wsh[qq][0]*xcb[(size_t)ish[qq][0]*C_XC + d]
              + wsh[qq][1]*xcb[(size_t)ish[qq][1]*C_XC + d]
              + wsh[qq][2]*xcb[(size_t)ish[qq][2]*C_XC + d];
        } else {
            v = prv[((size_t)b*Nq + q0 + qq)*C_PRV + (d - C_XC)];
        }
        featT[e] = v;
    }
    __syncthreads();
    int j0 = 2*threadIdx.x;
    u64 a0[8], a1[8];
    {
        float2 bb = *reinterpret_cast<const float2*>(&bias[j0]);
        u64 p0 = pack2(bb.x, bb.x), p1 = pack2(bb.y, bb.y);
        #pragma unroll
        for (int i = 0; i < 8; i++) { a0[i] = p0; a1[i] = p1; }
    }
    #pragma unroll 2
    for (int d = 0; d < CIN; d++) {
        ulonglong2 w = *reinterpret_cast<const ulonglong2*>(Wd + 2*(d*C_OUT + j0));
        const ulonglong2* f = reinterpret_cast<const ulonglong2*>(featT + d*QT);
        ulonglong2 f0 = f[0], f1 = f[1], f2 = f[2], f3 = f[3];
        a0[0]=ffma2(f0.x,w.x,a0[0]); a0[1]=ffma2(f0.y,w.x,a0[1]);
        a0[2]=ffma2(f1.x,w.x,a0[2]); a0[3]=ffma2(f1.y,w.x,a0[3]);
        a0[4]=ffma2(f2.x,w.x,a0[4]); a0[5]=ffma2(f2.y,w.x,a0[5]);
        a0[6]=ffma2(f3.x,w.x,a0[6]); a0[7]=ffma2(f3.y,w.x,a0[7]);
        a1[0]=ffma2(f0.x,w.y,a1[0]); a1[1]=ffma2(f0.y,w.y,a1[1]);
        a1[2]=ffma2(f1.x,w.y,a1[2]); a1[3]=ffma2(f1.y,w.y,a1[3]);
        a1[4]=ffma2(f2.x,w.y,a1[4]); a1[5]=ffma2(f2.y,w.y,a1[5]);
        a1[6]=ffma2(f3.x,w.y,a1[6]); a1[7]=ffma2(f3.y,w.y,a1[7]);
    }
    size_t obase = ((size_t)b*Nq + q0)*C_OUT + j0;
    #pragma unroll
    for (int i = 0; i < 8; i++) {
        float2 x = unpack2(a0[i]), y = unpack2(a1[i]);
        *reinterpret_cast<float2*>(&out[obase + (size_t)(2*i+0)*C_OUT]) =
            make_float2(fmaxf(x.x,0.f), fmaxf(y.x,0.f));
        *reinterpret_cast<float2*>(&out[obase + (size_t)(2*i+1)*C_OUT]) =
            make_float2(fmaxf(x.y,0.f), fmaxf(y.y,0.f));
    }
}

// ---------------- fused: up2 + final MLP ----------------
__global__ void up2_final_kernel(const float* __restrict__ up1,
                                 const float* __restrict__ x0, const float* __restrict__ pos0,
                                 const int* __restrict__ idx, const float* __restrict__ d2,
                                 const float* __restrict__ u2Wd, const float* __restrict__ u2b,
                                 const float* __restrict__ fW1d, const float* __restrict__ fb1,
                                 const float* __restrict__ fW2d, const float* __restrict__ fb2,
                                 float* __restrict__ out) {
    constexpr int QT = 16;
    __shared__ float featT[134*QT];
    __shared__ float h1T[128*QT];
    __shared__ float wsh[QT][3];
    __shared__ int   ish[QT][3];
    int b = blockIdx.y;
    int q0 = blockIdx.x * QT;
    if (threadIdx.x < QT) {
        int q = q0 + threadIdx.x;
        size_t base = ((size_t)b*NN0 + q)*3;
        float w0 = 1.0f/(d2[base+0] + 1e-8f);
        float w1 = 1.0f/(d2[base+1] + 1e-8f);
        float w2 = 1.0f/(d2[base+2] + 1e-8f);
        float s = w0 + w1 + w2;
        wsh[threadIdx.x][0] = w0/s; wsh[threadIdx.x][1] = w1/s; wsh[threadIdx.x][2] = w2/s;
        ish[threadIdx.x][0] = idx[base+0]; ish[threadIdx.x][1] = idx[base+1]; ish[threadIdx.x][2] = idx[base+2];
    }
    __syncthreads();
    const float* xcb = up1 + (size_t)b*NN1*128;
    for (int e = threadIdx.x; e < 134*QT; e += 64) {
        int d = e >> 4, qq = e & 15;
        float v;
        if (d < 128) {
            v = wsh[qq][0]*xcb[(size_t)ish[qq][0]*128 + d]
              + wsh[qq][1]*xcb[(size_t)ish[qq][1]*128 + d]
              + wsh[qq][2]*xcb[(size_t)ish[qq][2]*128 + d];
        } else if (d < 131) {
            v = x0  [((size_t)b*NN0 + q0 + qq)*3 + (d-128)];
        } else {
            v = pos0[((size_t)b*NN0 + q0 + qq)*3 + (d-131)];
        }
        featT[e] = v;
    }
    __syncthreads();
    int j0 = 2*threadIdx.x;
    u64 a0[8], a1[8];

    // ---- stage u2: 134 -> 128, relu ----
    {
        float2 bb = *reinterpret_cast<const float2*>(&u2b[j0]);
        u64 p0 = pack2(bb.x, bb.x), p1 = pack2(bb.y, bb.y);
        #pragma unroll
        for (int i = 0; i < 8; i++) { a0[i] = p0; a1[i] = p1; }
    }
    #pragma unroll 2
    for (int d = 0; d < 134; d++) {
        ulonglong2 w = *reinterpret_cast<const ulonglong2*>(u2Wd + 2*(d*128 + j0));
        const ulonglong2* f = reinterpret_cast<const ulonglong2*>(featT + d*QT);
        ulonglong2 f0 = f[0], f1 = f[1], f2 = f[2], f3 = f[3];
        a0[0]=ffma2(f0.x,w.x,a0[0]); a0[1]=ffma2(f0.y,w.x,a0[1]);
        a0[2]=ffma2(f1.x,w.x,a0[2]); a0[3]=ffma2(f1.y,w.x,a0[3]);
        a0[4]=ffma2(f2.x,w.x,a0[4]); a0[5]=ffma2(f2.y,w.x,a0[5]);
        a0[6]=ffma2(f3.x,w.x,a0[6]); a0[7]=ffma2(f3.y,w.x,a0[7]);
        a1[0]=ffma2(f0.x,w.y,a1[0]); a1[1]=ffma2(f0.y,w.y,a1[1]);
        a1[2]=ffma2(f1.x,w.y,a1[2]); a1[3]=ffma2(f1.y,w.y,a1[3]);
        a1[4]=ffma2(f2.x,w.y,a1[4]); a1[5]=ffma2(f2.y,w.y,a1[5]);
        a1[6]=ffma2(f3.x,w.y,a1[6]); a1[7]=ffma2(f3.y,w.y,a1[7]);
    }
    {
        float4* h0 = reinterpret_cast<float4*>(h1T + (size_t)j0*QT);
        float4* h1 = reinterpret_cast<float4*>(h1T + (size_t)(j0+1)*QT);
        #pragma unroll
        for (int i = 0; i < 4; i++) {
            float2 x0v = unpack2(a0[2*i]), x1v = unpack2(a0[2*i+1]);
            h0[i] = make_float4(fmaxf(x0v.x,0.f), fmaxf(x0v.y,0.f), fmaxf(x1v.x,0.f), fmaxf(x1v.y,0.f));
            float2 y0v = unpack2(a1[2*i]), y1v = unpack2(a1[2*i+1]);
            h1[i] = make_float4(fmaxf(y0v.x,0.f), fmaxf(y0v.y,0.f), fmaxf(y1v.x,0.f), fmaxf(y1v.y,0.f));
        }
    }
    __syncthreads();

    // ---- stage f1: 128 -> 128, relu (into featT) ----
    {
        float2 bb = *reinterpret_cast<const float2*>(&fb1[j0]);
        u64 p0 = pack2(bb.x, bb.x), p1 = pack2(bb.y, bb.y);
        #pragma unroll
        for (int i = 0; i < 8; i++) { a0[i] = p0; a1[i] = p1; }
    }
    #pragma unroll 2
    for (int d = 0; d < 128; d++) {
        ulonglong2 w = *reinterpret_cast<const ulonglong2*>(fW1d + 2*(d*128 + j0));
        const ulonglong2* f = reinterpret_cast<const ulonglong2*>(h1T + d*QT);
        ulonglong2 f0 = f[0], f1 = f[1], f2 = f[2], f3 = f[3];
        a0[0]=ffma2(f0.x,w.x,a0[0]); a0[1]=ffma2(f0.y,w.x,a0[1]);
        a0[2]=ffma2(f1.x,w.x,a0[2]); a0[3]=ffma2(f1.y,w.x,a0[3]);
        a0[4]=ffma2(f2.x,w.x,a0[4]); a0[5]=ffma2(f2.y,w.x,a0[5]);
        a0[6]=ffma2(f3.x,w.x,a0[6]); a0[7]=ffma2(f3.y,w.x,a0[7]);
        a1[0]=ffma2(f0.x,w.y,a1[0]); a1[1]=ffma2(f0.y,w.y,a1[1]);
        a1[2]=ffma2(f1.x,w.y,a1[2]); a1[3]=ffma2(f1.y,w.y,a1[3]);
        a1[4]=ffma2(f2.x,w.y,a1[4]); a1[5]=ffma2(f2.y,w.y,a1[5]);
        a1[6]=ffma2(f3.x,w.y,a1[6]); a1[7]=ffma2(f3.y,w.y,a1[7]);
    }
    __syncthreads();
    {
        float4* h0 = reinterpret_cast<float4*>(featT + (size_t)j0*QT);
        float4* h1 = reinterpret_cast<float4*>(featT + (size_t)(j0+1)*QT);
        #pragma unroll
        for (int i = 0; i < 4; i++) {
            float2 x0v = unpack2(a0[2*i]), x1v = unpack2(a0[2*i+1]);
            h0[i] = make_float4(fmaxf(x0v.x,0.f), fmaxf(x0v.y,0.f), fmaxf(x1v.x,0.f), fmaxf(x1v.y,0.f));
            float2 y0v = unpack2(a1[2*i]), y1v = unpack2(a1[2*i+1]);
            h1[i] = make_float4(fmaxf(y0v.x,0.f), fmaxf(y0v.y,0.f), fmaxf(y1v.x,0.f), fmaxf(y1v.y,0.f));
        }
    }
    __syncthreads();

    // ---- stage f2: 128 -> 128, no relu ----
    {
        float2 bb = *reinterpret_cast<const float2*>(&fb2[j0]);
        u64 p0 = pack2(bb.x, bb.x), p1 = pack2(bb.y, bb.y);
        #pragma unroll
        for (int i = 0; i < 8; i++) { a0[i] = p0; a1[i] = p1; }
    }
    #pragma unroll 2
    for (int d = 0; d < 128; d++) {
        ulonglong2 w = *reinterpret_cast<const ulonglong2*>(fW2d + 2*(d*128 + j0));
        const ulonglong2* f = reinterpret_cast<const ulonglong2*>(featT + d*QT);
        ulonglong2 f0 = f[0], f1 = f[1], f2 = f[2], f3 = f[3];
        a0[0]=ffma2(f0.x,w.x,a0[0]); a0[1]=ffma2(f0.y,w.x,a0[1]);
        a0[2]=ffma2(f1.x,w.x,a0[2]); a0[3]=ffma2(f1.y,w.x,a0[3]);
        a0[4]=ffma2(f2.x,w.x,a0[4]); a0[5]=ffma2(f2.y,w.x,a0[5]);
        a0[6]=ffma2(f3.x,w.x,a0[6]); a0[7]=ffma2(f3.y,w.x,a0[7]);
        a1[0]=ffma2(f0.x,w.y,a1[0]); a1[1]=ffma2(f0.y,w.y,a1[1]);
        a1[2]=ffma2(f1.x,w.y,a1[2]); a1[3]=ffma2(f1.y,w.y,a1[3]);
        a1[4]=ffma2(f2.x,w.y,a1[4]); a1[5]=ffma2(f2.y,w.y,a1[5]);
        a1[6]=ffma2(f3.x,w.y,a1[6]); a1[7]=ffma2(f3.y,w.y,a1[7]);
    }
    size_t obase = ((size_t)b*NN0 + q0)*128 + j0;
    #pragma unroll
    for (int i = 0; i < 8; i++) {
        float2 x = unpack2(a0[i]), y = unpack2(a1[i]);
        *reinterpret_cast<float2*>(&out[obase + (size_t)(2*i+0)*128]) = make_float2(x.x, y.x);
        *reinterpret_cast<float2*>(&out[obase + (size_t)(2*i+1)*128]) = make_float2(x.y, y.y);
    }
}

// ---------------- host launch ----------------
extern "C" void kernel_launch(void* const* d_in, const int* in_sizes, int n_in,
                              void* d_out, int out_size) {
    const float* x    = (const float*)d_in[0];
    const float* pos  = (const float*)d_in[1];
    const float* d0W1 = (const float*)d_in[2];
    const float* d0b1 = (const float*)d_in[3];
    const float* d0W2 = (const float*)d_in[4];
    const float* d0b2 = (const float*)d_in[5];
    const float* d1W1 = (const float*)d_in[6];
    const float* d1b1 = (const float*)d_in[7];
    const float* d1W2 = (const float*)d_in[8];
    const float* d1b2 = (const float*)d_in[9];
    const float* d2W1 = (const float*)d_in[10];
    const float* d2b1 = (const float*)d_in[11];
    const float* d2W2 = (const float*)d_in[12];
    const float* d2b2 = (const float*)d_in[13];
    const float* u0W  = (const float*)d_in[14];
    const float* u0b  = (const float*)d_in[15];
    const float* u1W  = (const float*)d_in[16];
    const float* u1b  = (const float*)d_in[17];
    const float* u2W  = (const float*)d_in[18];
    const float* u2b  = (const float*)d_in[19];
    const float* fW1  = (const float*)d_in[20];
    const float* fb1  = (const float*)d_in[21];
    const float* fW2  = (const float*)d_in[22];
    const float* fb2  = (const float*)d_in[23];
    float* out = (float*)d_out;

    int *idx0, *idx1, *idx2, *uidx0, *uidx1, *uidx2;
    float *ud20, *ud21, *ud22, *x1, *x2, *x3, *up0, *up1, *wd;
    cudaGetSymbolAddress((void**)&idx0,  g_idx0);
    cudaGetSymbolAddress((void**)&idx1,  g_idx1);
    cudaGetSymbolAddress((void**)&idx2,  g_idx2);
    cudaGetSymbolAddress((void**)&uidx0, g_uidx0);
    cudaGetSymbolAddress((void**)&uidx1, g_uidx1);
    cudaGetSymbolAddress((void**)&uidx2, g_uidx2);
    cudaGetSymbolAddress((void**)&ud20,  g_ud20);
    cudaGetSymbolAddress((void**)&ud21,  g_ud21);
    cudaGetSymbolAddress((void**)&ud22,  g_ud22);
    cudaGetSymbolAddress((void**)&x1,    g_x1);
    cudaGetSymbolAddress((void**)&x2,    g_x2);
    cudaGetSymbolAddress((void**)&x3,    g_x3);
    cudaGetSymbolAddress((void**)&up0,   g_up0);
    cudaGetSymbolAddress((void**)&up1,   g_up1);
    cudaGetSymbolAddress((void**)&wd,    g_wdup);

    const float* d0W1d = wd + 2*OFF_D0W1;
    const float* d0W2d = wd + 2*OFF_D0W2;
    const float* d1W1d = wd + 2*OFF_D1W1;
    const float* d1W2d = wd + 2*OFF_D1W2;
    const float* d2W1d = wd + 2*OFF_D2W1;
    const float* d2W2d = wd + 2*OFF_D2W2;
    const float* u0Wd  = wd + 2*OFF_U0W;
    const float* u1Wd  = wd + 2*OFF_U1W;
    const float* u2Wd  = wd + 2*OFF_U2W;
    const float* fW1d  = wd + 2*OFF_FW1;
    const float* fW2d  = wd + 2*OFF_FW2;

    cudaFuncSetAttribute((const void*)down4_kernel<256,512>,
                         cudaFuncAttributeMaxDynamicSharedMemorySize, 56*1024);
    cudaFuncSetAttribute((const void*)up_kernel<512,256,256>,
                         cudaFuncAttributeMaxDynamicSharedMemorySize, 50*1024);

    // ---- side stream for all KNN work (capture fork-join via events) ----
    cudaStream_t s;
    cudaStreamCreateWithFlags(&s, cudaStreamNonBlocking);
    cudaEvent_t eF, e0, e1, e2, e3, e4, e5;
    cudaEventCreateWithFlags(&eF, cudaEventDisableTiming);
    cudaEventCreateWithFlags(&e0, cudaEventDisableTiming);
    cudaEventCreateWithFlags(&e1, cudaEventDisableTiming);
    cudaEventCreateWithFlags(&e2, cudaEventDisableTiming);
    cudaEventCreateWithFlags(&e3, cudaEventDisableTiming);
    cudaEventCreateWithFlags(&e4, cudaEventDisableTiming);
    cudaEventCreateWithFlags(&e5, cudaEventDisableTiming);

    cudaEventRecord(eF, 0);
    cudaStreamWaitEvent(s, eF, 0);

    // KNN chain on side stream (ordered by first use)
    knn16_kernel<16,16><<<dim3(NN1,Bz), 512, 0, s>>>(pos, pos, NN1, idx0);
    cudaEventRecord(e0, s);
    knn16_kernel<8,8><<<dim3(NN2,Bz), 256, 0, s>>>(pos, pos, NN2, idx1);
    cudaEventRecord(e1, s);
    knn16_kernel<2,8><<<dim3(NN3,Bz), 256, 0, s>>>(pos, pos, NN3, idx2);
    cudaEventRecord(e2, s);
    knn3_kernel<4><<<dim3(NN2/8,Bz), 256, 0, s>>>(pos, pos, NN2, uidx0, ud20);
    cudaEventRecord(e3, s);
    knn3_kernel<16><<<dim3(NN1/8,Bz), 256, 0, s>>>(pos, pos, NN1, uidx1, ud21);
    cudaEventRecord(e4, s);
    knn3b_kernel<8,8><<<dim3(NN0,Bz), 256, 0, s>>>(pos, pos, NN0, uidx2, ud22);
    cudaEventRecord(e5, s);

    // main chain
    dup_weights_kernel<<<(W_TOTAL+255)/256, 256>>>(
        d0W1,d0W2,d1W1,d1W2,d2W1,d2W2,u0W,u1W,u2W,fW1,fW2, wd);

    cudaStreamWaitEvent(0, e0, 0);
    down0_kernel<<<dim3(NN1/2,Bz), 128>>>(x, pos, idx0, d0W1d,d0b1, d0W2d,d0b2, x1);
    cudaStreamWaitEvent(0, e1, 0);
    down4_kernel<128,256><<<dim3(NN2,Bz), 64, (131*16 + 256*16)*sizeof(float)>>>(
        x1, pos, idx1, d1W1d,d1b1, d1W2d,d1b2, x2, NN2, NN1*128);
    cudaStreamWaitEvent(0, e2, 0);
    down4_kernel<256,512><<<dim3(NN3,Bz), 128, (259*16 + 512*16)*sizeof(float)>>>(
        x2, pos, idx2, d2W1d,d2b1, d2W2d,d2b2, x3, NN3, NN2*256);
    cudaStreamWaitEvent(0, e3, 0);
    up_kernel<512,256,256><<<dim3(NN2/16,Bz), 128, 768*16*sizeof(float)>>>(
        x3, x2, uidx0, ud20, u0Wd, u0b, up0, NN2, NN3);
    cudaStreamWaitEvent(0, e4, 0);
    up_kernel<256,128,128><<<dim3(NN1/16,Bz), 64, 384*16*sizeof(float)>>>(
        up0, x1, uidx1, ud21, u1Wd, u1b, up1, NN1, NN2);
    cudaStreamWaitEvent(0, e5, 0);
    up2_final_kernel<<<dim3(NN0/16,Bz), 64>>>(up1, x, pos, uidx2, ud22,
                                              u2Wd,u2b, fW1d,fb1, fW2d,fb2, out);

    // ---- second tuple element: pos0 passthrough ----
    if (out_size >= Bz*NN0*128 + Bz*NN0*3) {
        cudaMemcpyAsync(out + (size_t)Bz*NN0*128, pos,
                        (size_t)Bz*NN0*3*sizeof(float), cudaMemcpyDeviceToDevice);
    }
}

// round 6
// speedup vs baseline: 1.0056x; 1.0056x over previous
#include <cuda_runtime.h>
#include <cfloat>
#include <cstdint>

#define Bz 4
#define NN0 8192
#define NN1 2048
#define NN2 512
#define NN3 128

typedef unsigned long long u64;

__device__ __forceinline__ u64 pack2(float x, float y) {
    u64 r; asm("mov.b64 %0, {%1, %2};" : "=l"(r) : "f"(x), "f"(y)); return r;
}
__device__ __forceinline__ float2 unpack2(u64 v) {
    float2 r; asm("mov.b64 {%0, %1}, %2;" : "=f"(r.x), "=f"(r.y) : "l"(v)); return r;
}
__device__ __forceinline__ u64 ffma2(u64 a, u64 b, u64 c) {
    u64 d; asm("fma.rn.f32x2 %0, %1, %2, %3;" : "=l"(d) : "l"(a), "l"(b), "l"(c)); return d;
}
__device__ __forceinline__ unsigned ordf(float f) {
    unsigned b = __float_as_uint(f);
    return b ^ (((unsigned)((int)b >> 31)) | 0x80000000u);
}
__device__ __forceinline__ float unordf(unsigned m) {
    unsigned b = m ^ ((m & 0x80000000u) ? 0x80000000u : 0xffffffffu);
    return __uint_as_float(b);
}

// ---------------- scratch (allocation-free) ----------------
__device__ int   g_idx0[Bz*NN1*16];
__device__ int   g_idx1[Bz*NN2*16];
__device__ int   g_idx2[Bz*NN3*16];
__device__ int   g_uidx0[Bz*NN2*3];
__device__ float g_ud20 [Bz*NN2*3];
__device__ int   g_uidx1[Bz*NN1*3];
__device__ float g_ud21 [Bz*NN1*3];
__device__ int   g_uidx2[Bz*NN0*3];
__device__ float g_ud22 [Bz*NN0*3];
__device__ float g_x1 [Bz*NN1*128];
__device__ float g_x2 [Bz*NN2*256];
__device__ float g_x3 [Bz*NN3*512];
__device__ float g_up0[Bz*NN2*256];
__device__ float g_up1[Bz*NN1*128];
__device__ __align__(16) float g_wdup[2*806656];

#define OFF_D0W1 0
#define OFF_D0W2 768
#define OFF_D1W1 17152
#define OFF_D1W2 50688
#define OFF_D2W1 116224
#define OFF_D2W2 248832
#define OFF_U0W  510976
#define OFF_U1W  707584
#define OFF_U2W  756736
#define OFF_FW1  773888
#define OFF_FW2  790272
#define W_TOTAL  806656

// ---------------- weight duplication prep ----------------
__global__ void dup_weights_kernel(const float* __restrict__ s0, const float* __restrict__ s1,
                                   const float* __restrict__ s2, const float* __restrict__ s3,
                                   const float* __restrict__ s4, const float* __restrict__ s5,
                                   const float* __restrict__ s6, const float* __restrict__ s7,
                                   const float* __restrict__ s8, const float* __restrict__ s9,
                                   const float* __restrict__ s10, float* __restrict__ dst) {
    int gid = blockIdx.x*256 + threadIdx.x;
    if (gid >= W_TOTAL) return;
    const int offs[11] = {OFF_D0W1,OFF_D0W2,OFF_D1W1,OFF_D1W2,OFF_D2W1,OFF_D2W2,
                          OFF_U0W,OFF_U1W,OFF_U2W,OFF_FW1,OFF_FW2};
    const float* srcs[11] = {s0,s1,s2,s3,s4,s5,s6,s7,s8,s9,s10};
    int seg = 0;
    #pragma unroll
    for (int i = 1; i < 11; i++) seg = (gid >= offs[i]) ? i : seg;
    float v = srcs[seg][gid - offs[seg]];
    reinterpret_cast<float2*>(dst)[gid] = make_float2(v, v);
}

// ---------------- KNN K=16: 8 warps local-top16 + single-warp merge ----------------
// (validated faster than block-combine variant; removal fully unrolled -> regs stay regs)
template<int CNT, int NWARP>
__global__ void knn16_kernel(const float* __restrict__ qpos, const float* __restrict__ rpos,
                             int Nq, int* __restrict__ oidx) {
    __shared__ u64 skey[NWARP*16];
    int b = blockIdx.y, q = blockIdx.x;
    int lane = threadIdx.x & 31, w = threadIdx.x >> 5;
    const float* qp = qpos + ((size_t)b*NN0 + q)*3;
    float qx = qp[0], qy = qp[1], qz = qp[2];
    float qq = qx*qx + qy*qy + qz*qz;
    const float* rp = rpos + (size_t)b*NN0*3;
    int base = w*CNT*32;

    unsigned ud[CNT];
    unsigned lmin = 0xffffffffu; int lslot = 0;
    #pragma unroll
    for (int i = 0; i < CNT; i++) {
        int r = base + i*32 + lane;
        float rx = rp[3*r+0], ry = rp[3*r+1], rz = rp[3*r+2];
        float rr = rx*rx + ry*ry + rz*rz;
        float dt = qx*rx + qy*ry + qz*rz;
        unsigned u = ordf(qq + rr - 2.0f*dt);
        ud[i] = u;
        if (u < lmin) { lmin = u; lslot = i; }
    }
    for (int s = 0; s < 16; s++) {
        unsigned gmin = __reduce_min_sync(0xffffffffu, lmin);
        unsigned cand = (lmin == gmin) ? (unsigned)(lslot*32 + lane) : 0xffffffffu;
        unsigned rloc = __reduce_min_sync(0xffffffffu, cand);
        if (lane == 0) skey[w*16 + s] = ((u64)gmin << 32) | (unsigned)(base + rloc);
        if ((rloc & 31) == (unsigned)lane) {
            int slot = (int)(rloc >> 5);
            #pragma unroll
            for (int i = 0; i < CNT; i++) if (i == slot) ud[i] = 0xffffffffu;
            unsigned nm = 0xffffffffu; int ns = 0;
            #pragma unroll
            for (int i = 0; i < CNT; i++) if (ud[i] < nm) { nm = ud[i]; ns = i; }
            lmin = nm; lslot = ns;
        }
    }
    __syncthreads();
    if (w == 0) {
        u64 head = ~0ull; int ptr = 0;
        if (lane < NWARP) head = skey[lane*16];
        size_t obase = ((size_t)b*Nq + q)*16;
        for (int s = 0; s < 16; s++) {
            unsigned hi = (unsigned)(head >> 32);
            unsigned mh = __reduce_min_sync(0xffffffffu, hi);
            unsigned lo = (hi == mh) ? (unsigned)head : 0xffffffffu;
            unsigned ml = __reduce_min_sync(0xffffffffu, lo);
            if (lane == 0) oidx[obase + s] = (int)ml;
            u64 best = ((u64)mh << 32) | ml;
            if (head == best) {
                ptr++;
                head = (ptr < 16) ? skey[lane*16 + ptr] : ~0ull;
            }
        }
    }
}

// ---------------- KNN K=3, block variant (large Nr): local top-3 + merge ----------------
template<int CNT, int NWARP>
__global__ void knn3b_kernel(const float* __restrict__ qpos, const float* __restrict__ rpos,
                             int Nq, int* __restrict__ oidx, float* __restrict__ od2) {
    __shared__ u64 skey[NWARP*3];
    int b = blockIdx.y, q = blockIdx.x;
    int lane = threadIdx.x & 31, w = threadIdx.x >> 5;
    const float* qp = qpos + ((size_t)b*NN0 + q)*3;
    float qx = qp[0], qy = qp[1], qz = qp[2];
    float qq = qx*qx + qy*qy + qz*qz;
    const float* rp = rpos + (size_t)b*NN0*3;
    int base = w*CNT*32;

    unsigned ud[CNT];
    unsigned lmin = 0xffffffffu; int lslot = 0;
    #pragma unroll
    for (int i = 0; i < CNT; i++) {
        int r = base + i*32 + lane;
        float rx = rp[3*r+0], ry = rp[3*r+1], rz = rp[3*r+2];
        float rr = rx*rx + ry*ry + rz*rz;
        float dt = qx*rx + qy*ry + qz*rz;
        unsigned u = ordf(qq + rr - 2.0f*dt);
        ud[i] = u;
        if (u < lmin) { lmin = u; lslot = i; }
    }
    #pragma unroll
    for (int s = 0; s < 3; s++) {
        unsigned gmin = __reduce_min_sync(0xffffffffu, lmin);
        unsigned cand = (lmin == gmin) ? (unsigned)(lslot*32 + lane) : 0xffffffffu;
        unsigned rloc = __reduce_min_sync(0xffffffffu, cand);
        if (lane == 0) skey[w*3 + s] = ((u64)gmin << 32) | (unsigned)(base + rloc);
        if (s < 2 && (rloc & 31) == (unsigned)lane) {
            int slot = (int)(rloc >> 5);
            #pragma unroll
            for (int i = 0; i < CNT; i++) if (i == slot) ud[i] = 0xffffffffu;
            unsigned nm = 0xffffffffu; int ns = 0;
            #pragma unroll
            for (int i = 0; i < CNT; i++) if (ud[i] < nm) { nm = ud[i]; ns = i; }
            lmin = nm; lslot = ns;
        }
    }
    __syncthreads();
    if (w == 0) {
        u64 head = ~0ull; int ptr = 0;
        if (lane < NWARP) head = skey[lane*3];
        size_t obase = ((size_t)b*Nq + q)*3;
        #pragma unroll
        for (int s = 0; s < 3; s++) {
            unsigned hi = (unsigned)(head >> 32);
            unsigned mh = __reduce_min_sync(0xffffffffu, hi);
            unsigned lo = (hi == mh) ? (unsigned)head : 0xffffffffu;
            unsigned ml = __reduce_min_sync(0xffffffffu, lo);
            if (lane == 0) {
                oidx[obase + s] = (int)ml;
                od2[obase + s]  = fmaxf(unordf(mh), 0.0f);
            }
            u64 best = ((u64)mh << 32) | ml;
            if (head == best) {
                ptr++;
                head = (ptr < 3) ? skey[lane*3 + ptr] : ~0ull;
            }
        }
    }
}

// ---------------- KNN K=3, warp variant (small Nr): one warp per query ----------------
template<int CNT>
__global__ void knn3_kernel(const float* __restrict__ qpos, const float* __restrict__ rpos,
                            int Nq, int* __restrict__ oidx, float* __restrict__ od2) {
    int b = blockIdx.y;
    int lane = threadIdx.x & 31;
    int q = blockIdx.x*8 + (threadIdx.x >> 5);
    const float* qp = qpos + ((size_t)b*NN0 + q)*3;
    float qx = qp[0], qy = qp[1], qz = qp[2];
    float qq = qx*qx + qy*qy + qz*qz;
    const float* rp = rpos + (size_t)b*NN0*3;

    unsigned ud[CNT];
    unsigned lmin = 0xffffffffu; int lslot = 0;
    #pragma unroll
    for (int i = 0; i < CNT; i++) {
        int r = i*32 + lane;
        float rx = rp[3*r+0], ry = rp[3*r+1], rz = rp[3*r+2];
        float rr = rx*rx + ry*ry + rz*rz;
        float dt = qx*rx + qy*ry + qz*rz;
        unsigned u = ordf(qq + rr - 2.0f*dt);
        ud[i] = u;
        if (u < lmin) { lmin = u; lslot = i; }
    }
    size_t obase = ((size_t)b*Nq + q)*3;
    #pragma unroll
    for (int s = 0; s < 3; s++) {
        unsigned gmin = __reduce_min_sync(0xffffffffu, lmin);
        unsigned cand = (lmin == gmin) ? (unsigned)(lslot*32 + lane) : 0xffffffffu;
        unsigned rwin = __reduce_min_sync(0xffffffffu, cand);
        if (lane == 0) {
            oidx[obase + s] = (int)rwin;
            od2[obase + s]  = fmaxf(unordf(gmin), 0.0f);
        }
        if (s < 2 && (rwin & 31) == (unsigned)lane) {
            int slot = (int)(rwin >> 5);
            #pragma unroll
            for (int i = 0; i < CNT; i++) if (i == slot) ud[i] = 0xffffffffu;
            unsigned nm = 0xffffffffu; int ns = 0;
            #pragma unroll
            for (int i = 0; i < CNT; i++) if (ud[i] < nm) { nm = ud[i]; ns = i; }
            lmin = nm; lslot = ns;
        }
    }
}

// ---------------- down: gather + 2-layer MLP + max over 16 neighbors (j-block=2) ----------------
template<int C_PREV, int C_HID>
__global__ void down_kernel(const float* __restrict__ xprev, const float* __restrict__ pos,
                            const int* __restrict__ idx,
                            const float* __restrict__ W1d, const float* __restrict__ b1,
                            const float* __restrict__ W2d, const float* __restrict__ b2,
                            float* __restrict__ xout, int Nq, int xbs) {
    constexpr int CIN = 3 + C_PREV;
    extern __shared__ float sm[];
    float* featT = sm;               // CIN*16
    float* hT    = sm + CIN*16;      // C_HID*16
    __shared__ int nbs[16];
    int b = blockIdx.y, q = blockIdx.x;
    if (threadIdx.x < 16) nbs[threadIdx.x] = idx[((size_t)b*Nq + q)*16 + threadIdx.x];
    __syncthreads();
    const float* rp = pos + (size_t)b*NN0*3;
    float cx = rp[3*q+0], cy = rp[3*q+1], cz = rp[3*q+2];
    const float* xp = xprev + (size_t)b*xbs;
    for (int e = threadIdx.x; e < 16*CIN; e += blockDim.x) {
        int d = e >> 4, k = e & 15;
        int nb = nbs[k];
        float v;
        if      (d == 0) v = rp[3*nb+0] - cx;
        else if (d == 1) v = rp[3*nb+1] - cy;
        else if (d == 2) v = rp[3*nb+2] - cz;
        else             v = xp[(size_t)nb*C_PREV + (d-3)];
        featT[d*16 + k] = v;
    }
    __syncthreads();
    int j0 = 2*threadIdx.x;
    u64 a0[8], a1[8];
    // ---- layer 1 ----
    {
        float2 bb = *reinterpret_cast<const float2*>(&b1[j0]);
        u64 p0 = pack2(bb.x, bb.x), p1 = pack2(bb.y, bb.y);
        #pragma unroll
        for (int i = 0; i < 8; i++) { a0[i] = p0; a1[i] = p1; }
    }
    #pragma unroll 2
    for (int d = 0; d < CIN; d++) {
        ulonglong2 w = *reinterpret_cast<const ulonglong2*>(W1d + 2*(d*C_HID + j0));
        const ulonglong2* f = reinterpret_cast<const ulonglong2*>(featT + d*16);
        ulonglong2 f0 = f[0], f1 = f[1], f2 = f[2], f3 = f[3];
        a0[0]=ffma2(f0.x,w.x,a0[0]); a0[1]=ffma2(f0.y,w.x,a0[1]);
        a0[2]=ffma2(f1.x,w.x,a0[2]); a0[3]=ffma2(f1.y,w.x,a0[3]);
        a0[4]=ffma2(f2.x,w.x,a0[4]); a0[5]=ffma2(f2.y,w.x,a0[5]);
        a0[6]=ffma2(f3.x,w.x,a0[6]); a0[7]=ffma2(f3.y,w.x,a0[7]);
        a1[0]=ffma2(f0.x,w.y,a1[0]); a1[1]=ffma2(f0.y,w.y,a1[1]);
        a1[2]=ffma2(f1.x,w.y,a1[2]); a1[3]=ffma2(f1.y,w.y,a1[3]);
        a1[4]=ffma2(f2.x,w.y,a1[4]); a1[5]=ffma2(f2.y,w.y,a1[5]);
        a1[6]=ffma2(f3.x,w.y,a1[6]); a1[7]=ffma2(f3.y,w.y,a1[7]);
    }
    {
        float4* h0 = reinterpret_cast<float4*>(hT + (size_t)j0*16);
        float4* h1 = reinterpret_cast<float4*>(hT + (size_t)(j0+1)*16);
        #pragma unroll
        for (int i = 0; i < 4; i++) {
            float2 x0 = unpack2(a0[2*i]), x1 = unpack2(a0[2*i+1]);
            h0[i] = make_float4(fmaxf(x0.x,0.f), fmaxf(x0.y,0.f), fmaxf(x1.x,0.f), fmaxf(x1.y,0.f));
            float2 y0 = unpack2(a1[2*i]), y1 = unpack2(a1[2*i+1]);
            h1[i] = make_float4(fmaxf(y0.x,0.f), fmaxf(y0.y,0.f), fmaxf(y1.x,0.f), fmaxf(y1.y,0.f));
        }
    }
    __syncthreads();
    // ---- layer 2 ----
    {
        float2 bb = *reinterpret_cast<const float2*>(&b2[j0]);
        u64 p0 = pack2(bb.x, bb.x), p1 = pack2(bb.y, bb.y);
        #pragma unroll
        for (int i = 0; i < 8; i++) { a0[i] = p0; a1[i] = p1; }
    }
    #pragma unroll 2
    for (int d = 0; d < C_HID; d++) {
        ulonglong2 w = *reinterpret_cast<const ulonglong2*>(W2d + 2*(d*C_HID + j0));
        const ulonglong2* f = reinterpret_cast<const ulonglong2*>(hT + d*16);
        ulonglong2 f0 = f[0], f1 = f[1], f2 = f[2], f3 = f[3];
        a0[0]=ffma2(f0.x,w.x,a0[0]); a0[1]=ffma2(f0.y,w.x,a0[1]);
        a0[2]=ffma2(f1.x,w.x,a0[2]); a0[3]=ffma2(f1.y,w.x,a0[3]);
        a0[4]=ffma2(f2.x,w.x,a0[4]); a0[5]=ffma2(f2.y,w.x,a0[5]);
        a0[6]=ffma2(f3.x,w.x,a0[6]); a0[7]=ffma2(f3.y,w.x,a0[7]);
        a1[0]=ffma2(f0.x,w.y,a1[0]); a1[1]=ffma2(f0.y,w.y,a1[1]);
        a1[2]=ffma2(f1.x,w.y,a1[2]); a1[3]=ffma2(f1.y,w.y,a1[3]);
        a1[4]=ffma2(f2.x,w.y,a1[4]); a1[5]=ffma2(f2.y,w.y,a1[5]);
        a1[6]=ffma2(f3.x,w.y,a1[6]); a1[7]=ffma2(f3.y,w.y,a1[7]);
    }
    // ---- max pool over 16 neighbors ----
    float m0 = -FLT_MAX, m1 = -FLT_MAX;
    #pragma unroll
    for (int i = 0; i < 8; i++) {
        float2 x = unpack2(a0[i]); m0 = fmaxf(m0, fmaxf(x.x, x.y));
        float2 y = unpack2(a1[i]); m1 = fmaxf(m1, fmaxf(y.x, y.y));
    }
    *reinterpret_cast<float2*>(&xout[((size_t)b*Nq + q)*C_HID + j0]) = make_float2(m0, m1);
}

// ---------------- up: 3-NN inverse-distance interp + cat + linear + relu ----------------
template<int C_XC, int C_PRV, int C_OUT>
__global__ void up_kernel(const float* __restrict__ xc, const float* __restrict__ prv,
                          const int* __restrict__ idx, const float* __restrict__ d2,
                          const float* __restrict__ Wd, const float* __restrict__ bias,
                          float* __restrict__ out, int Nq, int Nc) {
    constexpr int CIN = C_XC + C_PRV;
    constexpr int QT = 16;
    extern __shared__ float sm[];
    float* featT = sm;               // CIN * 16, [d][q]
    __shared__ float wsh[QT][3];
    __shared__ int   ish[QT][3];
    int b = blockIdx.y;
    int q0 = blockIdx.x * QT;
    if (threadIdx.x < QT) {
        int q = q0 + threadIdx.x;
        size_t base = ((size_t)b*Nq + q)*3;
        float w0 = 1.0f/(d2[base+0] + 1e-8f);
        float w1 = 1.0f/(d2[base+1] + 1e-8f);
        float w2 = 1.0f/(d2[base+2] + 1e-8f);
        float s = w0 + w1 + w2;
        wsh[threadIdx.x][0] = w0/s; wsh[threadIdx.x][1] = w1/s; wsh[threadIdx.x][2] = w2/s;
        ish[threadIdx.x][0] = idx[base+0]; ish[threadIdx.x][1] = idx[base+1]; ish[threadIdx.x][2] = idx[base+2];
    }
    __syncthreads();
    const float* xcb = xc + (size_t)b*Nc*C_XC;
    for (int e = threadIdx.x; e < CIN*QT; e += blockDim.x) {
        int d = e >> 4, qq = e & 15;
        float v;
        if (d < C_XC) {
            v = wsh[qq][0]*xcb[(size_t)ish[qq][0]*C_XC + d]
              + wsh[qq][1]*xcb[(size_t)ish[qq][1]*C_XC + d]
              + wsh[qq][2]*xcb[(size_t)ish[qq][2]*C_XC + d];
        } else {
            v = prv[((size_t)b*Nq + q0 + qq)*C_PRV + (d - C_XC)];
        }
        featT[e] = v;
    }
    __syncthreads();
    int j0 = 2*threadIdx.x;
    u64 a0[8], a1[8];
    {
        float2 bb = *reinterpret_cast<const float2*>(&bias[j0]);
        u64 p0 = pack2(bb.x, bb.x), p1 = pack2(bb.y, bb.y);
        #pragma unroll
        for (int i = 0; i < 8; i++) { a0[i] = p0; a1[i] = p1; }
    }
    #pragma unroll 2
    for (int d = 0; d < CIN; d++) {
        ulonglong2 w = *reinterpret_cast<const ulonglong2*>(Wd + 2*(d*C_OUT + j0));
        const ulonglong2* f = reinterpret_cast<const ulonglong2*>(featT + d*QT);
        ulonglong2 f0 = f[0], f1 = f[1], f2 = f[2], f3 = f[3];
        a0[0]=ffma2(f0.x,w.x,a0[0]); a0[1]=ffma2(f0.y,w.x,a0[1]);
        a0[2]=ffma2(f1.x,w.x,a0[2]); a0[3]=ffma2(f1.y,w.x,a0[3]);
        a0[4]=ffma2(f2.x,w.x,a0[4]); a0[5]=ffma2(f2.y,w.x,a0[5]);
        a0[6]=ffma2(f3.x,w.x,a0[6]); a0[7]=ffma2(f3.y,w.x,a0[7]);
        a1[0]=ffma2(f0.x,w.y,a1[0]); a1[1]=ffma2(f0.y,w.y,a1[1]);
        a1[2]=ffma2(f1.x,w.y,a1[2]); a1[3]=ffma2(f1.y,w.y,a1[3]);
        a1[4]=ffma2(f2.x,w.y,a1[4]); a1[5]=ffma2(f2.y,w.y,a1[5]);
        a1[6]=ffma2(f3.x,w.y,a1[6]); a1[7]=ffma2(f3.y,w.y,a1[7]);
    }
    size_t obase = ((size_t)b*Nq + q0)*C_OUT + j0;
    #pragma unroll
    for (int i = 0; i < 8; i++) {
        float2 x = unpack2(a0[i]), y = unpack2(a1[i]);
        *reinterpret_cast<float2*>(&out[obase + (size_t)(2*i+0)*C_OUT]) =
            make_float2(fmaxf(x.x,0.f), fmaxf(y.x,0.f));
        *reinterpret_cast<float2*>(&out[obase + (size_t)(2*i+1)*C_OUT]) =
            make_float2(fmaxf(x.y,0.f), fmaxf(y.y,0.f));
    }
}

// ---------------- fused: up2 + final MLP ----------------
__global__ void up2_final_kernel(const float* __restrict__ up1,
                                 const float* __restrict__ x0, const float* __restrict__ pos0,
                                 const int* __restrict__ idx, const float* __restrict__ d2,
                                 const float* __restrict__ u2Wd, const float* __restrict__ u2b,
                                 const float* __restrict__ fW1d, const float* __restrict__ fb1,
                                 const float* __restrict__ fW2d, const float* __restrict__ fb2,
                                 float* __restrict__ out) {
    constexpr int QT = 16;
    __shared__ float featT[134*QT];
    __shared__ float h1T[128*QT];
    __shared__ float wsh[QT][3];
    __shared__ int   ish[QT][3];
    int b = blockIdx.y;
    int q0 = blockIdx.x * QT;
    if (threadIdx.x < QT) {
        int q = q0 + threadIdx.x;
        size_t base = ((size_t)b*NN0 + q)*3;
        float w0 = 1.0f/(d2[base+0] + 1e-8f);
        float w1 = 1.0f/(d2[base+1] + 1e-8f);
        float w2 = 1.0f/(d2[base+2] + 1e-8f);
        float s = w0 + w1 + w2;
        wsh[threadIdx.x][0] = w0/s; wsh[threadIdx.x][1] = w1/s; wsh[threadIdx.x][2] = w2/s;
        ish[threadIdx.x][0] = idx[base+0]; ish[threadIdx.x][1] = idx[base+1]; ish[threadIdx.x][2] = idx[base+2];
    }
    __syncthreads();
    const float* xcb = up1 + (size_t)b*NN1*128;
    for (int e = threadIdx.x; e < 134*QT; e += 64) {
        int d = e >> 4, qq = e & 15;
        float v;
        if (d < 128) {
            v = wsh[qq][0]*xcb[(size_t)ish[qq][0]*128 + d]
              + wsh[qq][1]*xcb[(size_t)ish[qq][1]*128 + d]
              + wsh[qq][2]*xcb[(size_t)ish[qq][2]*128 + d];
        } else if (d < 131) {
            v = x0  [((size_t)b*NN0 + q0 + qq)*3 + (d-128)];
        } else {
            v = pos0[((size_t)b*NN0 + q0 + qq)*3 + (d-131)];
        }
        featT[e] = v;
    }
    __syncthreads();
    int j0 = 2*threadIdx.x;
    u64 a0[8], a1[8];

    // ---- stage u2: 134 -> 128, relu ----
    {
        float2 bb = *reinterpret_cast<const float2*>(&u2b[j0]);
        u64 p0 = pack2(bb.x, bb.x), p1 = pack2(bb.y, bb.y);
        #pragma unroll
        for (int i = 0; i < 8; i++) { a0[i] = p0; a1[i] = p1; }
    }
    #pragma unroll 2
    for (int d = 0; d < 134; d++) {
        ulonglong2 w = *reinterpret_cast<const ulonglong2*>(u2Wd + 2*(d*128 + j0));
        const ulonglong2* f = reinterpret_cast<const ulonglong2*>(featT + d*QT);
        ulonglong2 f0 = f[0], f1 = f[1], f2 = f[2], f3 = f[3];
        a0[0]=ffma2(f0.x,w.x,a0[0]); a0[1]=ffma2(f0.y,w.x,a0[1]);
        a0[2]=ffma2(f1.x,w.x,a0[2]); a0[3]=ffma2(f1.y,w.x,a0[3]);
        a0[4]=ffma2(f2.x,w.x,a0[4]); a0[5]=ffma2(f2.y,w.x,a0[5]);
        a0[6]=ffma2(f3.x,w.x,a0[6]); a0[7]=ffma2(f3.y,w.x,a0[7]);
        a1[0]=ffma2(f0.x,w.y,a1[0]); a1[1]=ffma2(f0.y,w.y,a1[1]);
        a1[2]=ffma2(f1.x,w.y,a1[2]); a1[3]=ffma2(f1.y,w.y,a1[3]);
        a1[4]=ffma2(f2.x,w.y,a1[4]); a1[5]=ffma2(f2.y,w.y,a1[5]);
        a1[6]=ffma2(f3.x,w.y,a1[6]); a1[7]=ffma2(f3.y,w.y,a1[7]);
    }
    {
        float4* h0 = reinterpret_cast<float4*>(h1T + (size_t)j0*QT);
        float4* h1 = reinterpret_cast<float4*>(h1T + (size_t)(j0+1)*QT);
        #pragma unroll
        for (int i = 0; i < 4; i++) {
            float2 x0v = unpack2(a0[2*i]), x1v = unpack2(a0[2*i+1]);
            h0[i] = make_float4(fmaxf(x0v.x,0.f), fmaxf(x0v.y,0.f), fmaxf(x1v.x,0.f), fmaxf(x1v.y,0.f));
            float2 y0v = unpack2(a1[2*i]), y1v = unpack2(a1[2*i+1]);
            h1[i] = make_float4(fmaxf(y0v.x,0.f), fmaxf(y0v.y,0.f), fmaxf(y1v.x,0.f), fmaxf(y1v.y,0.f));
        }
    }
    __syncthreads();

    // ---- stage f1: 128 -> 128, relu (into featT) ----
    {
        float2 bb = *reinterpret_cast<const float2*>(&fb1[j0]);
        u64 p0 = pack2(bb.x, bb.x), p1 = pack2(bb.y, bb.y);
        #pragma unroll
        for (int i = 0; i < 8; i++) { a0[i] = p0; a1[i] = p1; }
    }
    #pragma unroll 2
    for (int d = 0; d < 128; d++) {
        ulonglong2 w = *reinterpret_cast<const ulonglong2*>(fW1d + 2*(d*128 + j0));
        const ulonglong2* f = reinterpret_cast<const ulonglong2*>(h1T + d*QT);
        ulonglong2 f0 = f[0], f1 = f[1], f2 = f[2], f3 = f[3];
        a0[0]=ffma2(f0.x,w.x,a0[0]); a0[1]=ffma2(f0.y,w.x,a0[1]);
        a0[2]=ffma2(f1.x,w.x,a0[2]); a0[3]=ffma2(f1.y,w.x,a0[3]);
        a0[4]=ffma2(f2.x,w.x,a0[4]); a0[5]=ffma2(f2.y,w.x,a0[5]);
        a0[6]=ffma2(f3.x,w.x,a0[6]); a0[7]=ffma2(f3.y,w.x,a0[7]);
        a1[0]=ffma2(f0.x,w.y,a1[0]); a1[1]=ffma2(f0.y,w.y,a1[1]);
        a1[2]=ffma2(f1.x,w.y,a1[2]); a1[3]=ffma2(f1.y,w.y,a1[3]);
        a1[4]=ffma2(f2.x,w.y,a1[4]); a1[5]=ffma2(f2.y,w.y,a1[5]);
        a1[6]=ffma2(f3.x,w.y,a1[6]); a1[7]=ffma2(f3.y,w.y,a1[7]);
    }
    __syncthreads();
    {
        float4* h0 = reinterpret_cast<float4*>(featT + (size_t)j0*QT);
        float4* h1 = reinterpret_cast<float4*>(featT + (size_t)(j0+1)*QT);
        #pragma unroll
        for (int i = 0; i < 4; i++) {
            float2 x0v = unpack2(a0[2*i]), x1v = unpack2(a0[2*i+1]);
            h0[i] = make_float4(fmaxf(x0v.x,0.f), fmaxf(x0v.y,0.f), fmaxf(x1v.x,0.f), fmaxf(x1v.y,0.f));
            float2 y0v = unpack2(a1[2*i]), y1v = unpack2(a1[2*i+1]);
            h1[i] = make_float4(fmaxf(y0v.x,0.f), fmaxf(y0v.y,0.f), fmaxf(y1v.x,0.f), fmaxf(y1v.y,0.f));
        }
    }
    __syncthreads();

    // ---- stage f2: 128 -> 128, no relu ----
    {
        float2 bb = *reinterpret_cast<const float2*>(&fb2[j0]);
        u64 p0 = pack2(bb.x, bb.x), p1 = pack2(bb.y, bb.y);
        #pragma unroll
        for (int i = 0; i < 8; i++) { a0[i] = p0; a1[i] = p1; }
    }
    #pragma unroll 2
    for (int d = 0; d < 128; d++) {
        ulonglong2 w = *reinterpret_cast<const ulonglong2*>(fW2d + 2*(d*128 + j0));
        const ulonglong2* f = reinterpret_cast<const ulonglong2*>(featT + d*QT);
        ulonglong2 f0 = f[0], f1 = f[1], f2 = f[2], f3 = f[3];
        a0[0]=ffma2(f0.x,w.x,a0[0]); a0[1]=ffma2(f0.y,w.x,a0[1]);
        a0[2]=ffma2(f1.x,w.x,a0[2]); a0[3]=ffma2(f1.y,w.x,a0[3]);
        a0[4]=ffma2(f2.x,w.x,a0[4]); a0[5]=ffma2(f2.y,w.x,a0[5]);
        a0[6]=ffma2(f3.x,w.x,a0[6]); a0[7]=ffma2(f3.y,w.x,a0[7]);
        a1[0]=ffma2(f0.x,w.y,a1[0]); a1[1]=ffma2(f0.y,w.y,a1[1]);
        a1[2]=ffma2(f1.x,w.y,a1[2]); a1[3]=ffma2(f1.y,w.y,a1[3]);
        a1[4]=ffma2(f2.x,w.y,a1[4]); a1[5]=ffma2(f2.y,w.y,a1[5]);
        a1[6]=ffma2(f3.x,w.y,a1[6]); a1[7]=ffma2(f3.y,w.y,a1[7]);
    }
    size_t obase = ((size_t)b*NN0 + q0)*128 + j0;
    #pragma unroll
    for (int i = 0; i < 8; i++) {
        float2 x = unpack2(a0[i]), y = unpack2(a1[i]);
        *reinterpret_cast<float2*>(&out[obase + (size_t)(2*i+0)*128]) = make_float2(x.x, y.x);
        *reinterpret_cast<float2*>(&out[obase + (size_t)(2*i+1)*128]) = make_float2(x.y, y.y);
    }
}

// ---------------- host launch ----------------
extern "C" void kernel_launch(void* const* d_in, const int* in_sizes, int n_in,
                              void* d_out, int out_size) {
    const float* x    = (const float*)d_in[0];
    const float* pos  = (const float*)d_in[1];
    const float* d0W1 = (const float*)d_in[2];
    const float* d0b1 = (const float*)d_in[3];
    const float* d0W2 = (const float*)d_in[4];
    const float* d0b2 = (const float*)d_in[5];
    const float* d1W1 = (const float*)d_in[6];
    const float* d1b1 = (const float*)d_in[7];
    const float* d1W2 = (const float*)d_in[8];
    const float* d1b2 = (const float*)d_in[9];
    const float* d2W1 = (const float*)d_in[10];
    const float* d2b1 = (const float*)d_in[11];
    const float* d2W2 = (const float*)d_in[12];
    const float* d2b2 = (const float*)d_in[13];
    const float* u0W  = (const float*)d_in[14];
    const float* u0b  = (const float*)d_in[15];
    const float* u1W  = (const float*)d_in[16];
    const float* u1b  = (const float*)d_in[17];
    const float* u2W  = (const float*)d_in[18];
    const float* u2b  = (const float*)d_in[19];
    const float* fW1  = (const float*)d_in[20];
    const float* fb1  = (const float*)d_in[21];
    const float* fW2  = (const float*)d_in[22];
    const float* fb2  = (const float*)d_in[23];
    float* out = (float*)d_out;

    int *idx0, *idx1, *idx2, *uidx0, *uidx1, *uidx2;
    float *ud20, *ud21, *ud22, *x1, *x2, *x3, *up0, *up1, *wd;
    cudaGetSymbolAddress((void**)&idx0,  g_idx0);
    cudaGetSymbolAddress((void**)&idx1,  g_idx1);
    cudaGetSymbolAddress((void**)&idx2,  g_idx2);
    cudaGetSymbolAddress((void**)&uidx0, g_uidx0);
    cudaGetSymbolAddress((void**)&uidx1, g_uidx1);
    cudaGetSymbolAddress((void**)&uidx2, g_uidx2);
    cudaGetSymbolAddress((void**)&ud20,  g_ud20);
    cudaGetSymbolAddress((void**)&ud21,  g_ud21);
    cudaGetSymbolAddress((void**)&ud22,  g_ud22);
    cudaGetSymbolAddress((void**)&x1,    g_x1);
    cudaGetSymbolAddress((void**)&x2,    g_x2);
    cudaGetSymbolAddress((void**)&x3,    g_x3);
    cudaGetSymbolAddress((void**)&up0,   g_up0);
    cudaGetSymbolAddress((void**)&up1,   g_up1);
    cudaGetSymbolAddress((void**)&wd,    g_wdup);

    const float* d0W1d = wd + 2*OFF_D0W1;
    const float* d0W2d = wd + 2*OFF_D0W2;
    const float* d1W1d = wd + 2*OFF_D1W1;
    const float* d1W2d = wd + 2*OFF_D1W2;
    const float* d2W1d = wd + 2*OFF_D2W1;
    const float* d2W2d = wd + 2*OFF_D2W2;
    const float* u0Wd  = wd + 2*OFF_U0W;
    const float* u1Wd  = wd + 2*OFF_U1W;
    const float* u2Wd  = wd + 2*OFF_U2W;
    const float* fW1d  = wd + 2*OFF_FW1;
    const float* fW2d  = wd + 2*OFF_FW2;

    cudaFuncSetAttribute((const void*)down_kernel<256,512>,
                         cudaFuncAttributeMaxDynamicSharedMemorySize, 56*1024);
    cudaFuncSetAttribute((const void*)up_kernel<512,256,256>,
                         cudaFuncAttributeMaxDynamicSharedMemorySize, 50*1024);

    // ---- weight duplication prep ----
    dup_weights_kernel<<<(W_TOTAL+255)/256, 256>>>(
        d0W1,d0W2,d1W1,d1W2,d2W1,d2W2,u0W,u1W,u2W,fW1,fW2, wd);

    // ---- down 0: knn(2048 q, 8192 refs) + MLP ----
    knn16_kernel<32,8><<<dim3(NN1,Bz), 256>>>(pos, pos, NN1, idx0);
    down_kernel<3,128><<<dim3(NN1,Bz), 64, (6*16 + 128*16)*sizeof(float)>>>(
        x, pos, idx0, d0W1d,d0b1, d0W2d,d0b2, x1, NN1, NN0*3);
    // ---- down 1: knn(512 q, 2048 refs) + MLP ----
    knn16_kernel<8,8><<<dim3(NN2,Bz), 256>>>(pos, pos, NN2, idx1);
    down_kernel<128,256><<<dim3(NN2,Bz), 128, (131*16 + 256*16)*sizeof(float)>>>(
        x1, pos, idx1, d1W1d,d1b1, d1W2d,d1b2, x2, NN2, NN1*128);
    // ---- down 2: knn(128 q, 512 refs) + MLP ----
    knn16_kernel<2,8><<<dim3(NN3,Bz), 256>>>(pos, pos, NN3, idx2);
    down_kernel<256,512><<<dim3(NN3,Bz), 256, (259*16 + 512*16)*sizeof(float)>>>(
        x2, pos, idx2, d2W1d,d2b1, d2W2d,d2b2, x3, NN3, NN2*256);
    // ---- up 0: knn(512 q, 128 refs) + interp/MLP ----
    knn3_kernel<4><<<dim3(NN2/8,Bz), 256>>>(pos, pos, NN2, uidx0, ud20);
    up_kernel<512,256,256><<<dim3(NN2/16,Bz), 128, 768*16*sizeof(float)>>>(
        x3, x2, uidx0, ud20, u0Wd, u0b, up0, NN2, NN3);
    // ---- up 1: knn(2048 q, 512 refs) + interp/MLP ----
    knn3_kernel<16><<<dim3(NN1/8,Bz), 256>>>(pos, pos, NN1, uidx1, ud21);
    up_kernel<256,128,128><<<dim3(NN1/16,Bz), 64, 384*16*sizeof(float)>>>(
        up0, x1, uidx1, ud21, u1Wd, u1b, up1, NN1, NN2);
    // ---- up 2 + final MLP: knn(8192 q, 2048 refs) + fused ----
    knn3b_kernel<8,8><<<dim3(NN0,Bz), 256>>>(pos, pos, NN0, uidx2, ud22);
    up2_final_kernel<<<dim3(NN0/16,Bz), 64>>>(up1, x, pos, uidx2, ud22,
                                              u2Wd,u2b, fW1d,fb1, fW2d,fb2, out);
    // ---- second tuple element: pos0 passthrough ----
    if (out_size >= Bz*NN0*128 + Bz*NN0*3) {
        cudaMemcpyAsync(out + (size_t)Bz*NN0*128, pos,
                        (size_t)Bz*NN0*3*sizeof(float), cudaMemcpyDeviceToDevice);
    }
}

// round 7
// speedup vs baseline: 1.2199x; 1.2131x over previous
#include <cuda_runtime.h>
#include <cfloat>
#include <cstdint>

#define Bz 4
#define NN0 8192
#define NN1 2048
#define NN2 512
#define NN3 128

typedef unsigned long long u64;

__device__ __forceinline__ u64 pack2(float x, float y) {
    u64 r; asm("mov.b64 %0, {%1, %2};" : "=l"(r) : "f"(x), "f"(y)); return r;
}
__device__ __forceinline__ float2 unpack2(u64 v) {
    float2 r; asm("mov.b64 {%0, %1}, %2;" : "=f"(r.x), "=f"(r.y) : "l"(v)); return r;
}
__device__ __forceinline__ u64 ffma2(u64 a, u64 b, u64 c) {
    u64 d; asm("fma.rn.f32x2 %0, %1, %2, %3;" : "=l"(d) : "l"(a), "l"(b), "l"(c)); return d;
}
__device__ __forceinline__ unsigned ordf(float f) {
    unsigned b = __float_as_uint(f);
    return b ^ (((unsigned)((int)b >> 31)) | 0x80000000u);
}
__device__ __forceinline__ float unordf(unsigned m) {
    unsigned b = m ^ ((m & 0x80000000u) ? 0x80000000u : 0xffffffffu);
    return __uint_as_float(b);
}

// per-lane top-3 insertion (ascending). values unsigned ordf keys, slot shadows.
#define INS3(u, si) do { \
    bool p1 = (u) < m1v; \
    unsigned c1v = p1 ? m1v : (u);  int c1s = p1 ? m1s : (si); \
    m1v = p1 ? (u) : m1v;           m1s = p1 ? (si) : m1s; \
    bool p2 = c1v < m2v; \
    unsigned c2v = p2 ? m2v : c1v;  int c2s = p2 ? m2s : c1s; \
    m2v = p2 ? c1v : m2v;           m2s = p2 ? c1s : m2s; \
    bool p3 = c2v < m3v; \
    m3v = p3 ? c2v : m3v;           m3s = p3 ? c2s : m3s; \
} while(0)

// ---------------- scratch (allocation-free) ----------------
__device__ int   g_idx0[Bz*NN1*16];
__device__ int   g_idx1[Bz*NN2*16];
__device__ int   g_idx2[Bz*NN3*16];
__device__ int   g_uidx0[Bz*NN2*3];
__device__ float g_ud20 [Bz*NN2*3];
__device__ int   g_uidx1[Bz*NN1*3];
__device__ float g_ud21 [Bz*NN1*3];
__device__ int   g_uidx2[Bz*NN0*3];
__device__ float g_ud22 [Bz*NN0*3];
__device__ float g_x1 [Bz*NN1*128];
__device__ float g_x2 [Bz*NN2*256];
__device__ float g_x3 [Bz*NN3*512];
__device__ float g_up0[Bz*NN2*256];
__device__ float g_up1[Bz*NN1*128];
__device__ __align__(16) float g_wdup[2*806656];
__device__ __align__(16) float4 g_pos4[Bz*NN0];

#define OFF_D0W1 0
#define OFF_D0W2 768
#define OFF_D1W1 17152
#define OFF_D1W2 50688
#define OFF_D2W1 116224
#define OFF_D2W2 248832
#define OFF_U0W  510976
#define OFF_U1W  707584
#define OFF_U2W  756736
#define OFF_FW1  773888
#define OFF_FW2  790272
#define W_TOTAL  806656

// ---------------- prep: weight duplication ----------------
__global__ void dup_weights_kernel(const float* __restrict__ s0, const float* __restrict__ s1,
                                   const float* __restrict__ s2, const float* __restrict__ s3,
                                   const float* __restrict__ s4, const float* __restrict__ s5,
                                   const float* __restrict__ s6, const float* __restrict__ s7,
                                   const float* __restrict__ s8, const float* __restrict__ s9,
                                   const float* __restrict__ s10, float* __restrict__ dst) {
    int gid = blockIdx.x*256 + threadIdx.x;
    if (gid >= W_TOTAL) return;
    const int offs[11] = {OFF_D0W1,OFF_D0W2,OFF_D1W1,OFF_D1W2,OFF_D2W1,OFF_D2W2,
                          OFF_U0W,OFF_U1W,OFF_U2W,OFF_FW1,OFF_FW2};
    const float* srcs[11] = {s0,s1,s2,s3,s4,s5,s6,s7,s8,s9,s10};
    int seg = 0;
    #pragma unroll
    for (int i = 1; i < 11; i++) seg = (gid >= offs[i]) ? i : seg;
    float v = srcs[seg][gid - offs[seg]];
    reinterpret_cast<float2*>(dst)[gid] = make_float2(v, v);
}

// ---------------- prep: pos -> (x,y,z,|r|^2) ----------------
__global__ void prep_pos4_kernel(const float* __restrict__ pos, float4* __restrict__ out) {
    int i = blockIdx.x*256 + threadIdx.x;   // over Bz*NN0
    float x = pos[3*i+0], y = pos[3*i+1], z = pos[3*i+2];
    float rr = x*x + y*y + z*z;             // same expression/contraction as before
    out[i] = make_float4(x, y, z, rr);
}

// ---------------- KNN K=16: per-lane top-3 + rounds + single-warp merge ----------------
template<int CNT, int NWARP>
__global__ void knn16_kernel(const float4* __restrict__ pos4, int Nq, int* __restrict__ oidx) {
    __shared__ u64 skey[NWARP*16];
    int b = blockIdx.y, q = blockIdx.x;
    int lane = threadIdx.x & 31, w = threadIdx.x >> 5;
    const float4* rp = pos4 + (size_t)b*NN0;
    float4 qp = rp[q];
    float qx = qp.x, qy = qp.y, qz = qp.z, qq = qp.w;
    int base = w*CNT*32;

    unsigned ud[CNT];
    unsigned m1v = 0xffffffffu, m2v = 0xffffffffu, m3v = 0xffffffffu;
    int m1s = 0, m2s = 0, m3s = 0;
    #pragma unroll
    for (int i = 0; i < CNT; i++) {
        float4 r4 = rp[base + i*32 + lane];
        float dt = qx*r4.x + qy*r4.y + qz*r4.z;
        float dv = qq + r4.w - 2.0f*dt;
        unsigned u = ordf(dv);
        ud[i] = u;
        INS3(u, i);
    }
    for (int s = 0; s < 16; s++) {
        unsigned mh = __reduce_min_sync(0xffffffffu, m1v);
        unsigned cand = (m1v == mh) ? (unsigned)(m1s*32 + lane) : 0xffffffffu;
        unsigned ml = __reduce_min_sync(0xffffffffu, cand);
        if (lane == 0) skey[w*16 + s] = ((u64)mh << 32) | (unsigned)(base + (int)ml);
        if (cand == ml && m1v == mh) {
            unsigned thr = m1v;
            m1v = m2v; m1s = m2s;
            m2v = m3v; m2s = m3s;
            m3v = 0xffffffffu;
            if (m1v == 0xffffffffu) {   // exhausted buffer: exact rebuild above threshold
                m2v = 0xffffffffu; m3v = 0xffffffffu;
                #pragma unroll
                for (int i = 0; i < CNT; i++) {
                    unsigned u = ud[i];
                    if (u > thr) { INS3(u, i); }
                }
            }
        }
    }
    __syncthreads();
    // warp 0: NWARP-way merge of sorted 16-lists
    if (w == 0) {
        u64 head = ~0ull; int ptr = 0;
        if (lane < NWARP) head = skey[lane*16];
        size_t obase = ((size_t)b*Nq + q)*16;
        for (int s = 0; s < 16; s++) {
            unsigned hi = (unsigned)(head >> 32);
            unsigned mh = __reduce_min_sync(0xffffffffu, hi);
            unsigned lo = (hi == mh) ? (unsigned)head : 0xffffffffu;
            unsigned ml = __reduce_min_sync(0xffffffffu, lo);
            if (lane == 0) oidx[obase + s] = (int)ml;
            u64 best = ((u64)mh << 32) | ml;
            if (head == best) {
                ptr++;
                head = (ptr < 16) ? skey[lane*16 + ptr] : ~0ull;
            }
        }
    }
}

// ---------------- KNN K=3, block variant (large Nr): top-3 per lane, no fallback ----------------
template<int CNT, int NWARP>
__global__ void knn3b_kernel(const float4* __restrict__ pos4, int Nq,
                             int* __restrict__ oidx, float* __restrict__ od2) {
    __shared__ u64 skey[NWARP*3];
    int b = blockIdx.y, q = blockIdx.x;
    int lane = threadIdx.x & 31, w = threadIdx.x >> 5;
    const float4* rp = pos4 + (size_t)b*NN0;
    float4 qp = rp[q];
    float qx = qp.x, qy = qp.y, qz = qp.z, qq = qp.w;
    int base = w*CNT*32;

    unsigned m1v = 0xffffffffu, m2v = 0xffffffffu, m3v = 0xffffffffu;
    int m1s = 0, m2s = 0, m3s = 0;
    #pragma unroll
    for (int i = 0; i < CNT; i++) {
        float4 r4 = rp[base + i*32 + lane];
        float dt = qx*r4.x + qy*r4.y + qz*r4.z;
        float dv = qq + r4.w - 2.0f*dt;
        unsigned u = ordf(dv);
        INS3(u, i);
    }
    #pragma unroll
    for (int s = 0; s < 3; s++) {
        unsigned mh = __reduce_min_sync(0xffffffffu, m1v);
        unsigned cand = (m1v == mh) ? (unsigned)(m1s*32 + lane) : 0xffffffffu;
        unsigned ml = __reduce_min_sync(0xffffffffu, cand);
        if (lane == 0) skey[w*3 + s] = ((u64)mh << 32) | (unsigned)(base + (int)ml);
        if (cand == ml && m1v == mh) {
            m1v = m2v; m1s = m2s;
            m2v = m3v; m2s = m3s;
            m3v = 0xffffffffu;
        }
    }
    __syncthreads();
    if (w == 0) {
        u64 head = ~0ull; int ptr = 0;
        if (lane < NWARP) head = skey[lane*3];
        size_t obase = ((size_t)b*Nq + q)*3;
        #pragma unroll
        for (int s = 0; s < 3; s++) {
            unsigned hi = (unsigned)(head >> 32);
            unsigned mh = __reduce_min_sync(0xffffffffu, hi);
            unsigned lo = (hi == mh) ? (unsigned)head : 0xffffffffu;
            unsigned ml = __reduce_min_sync(0xffffffffu, lo);
            if (lane == 0) {
                oidx[obase + s] = (int)ml;
                od2[obase + s]  = fmaxf(unordf(mh), 0.0f);
            }
            u64 best = ((u64)mh << 32) | ml;
            if (head == best) {
                ptr++;
                head = (ptr < 3) ? skey[lane*3 + ptr] : ~0ull;
            }
        }
    }
}

// ---------------- KNN K=3, warp variant (small Nr): top-3 per lane ----------------
template<int CNT>
__global__ void knn3_kernel(const float4* __restrict__ pos4, int Nq,
                            int* __restrict__ oidx, float* __restrict__ od2) {
    int b = blockIdx.y;
    int lane = threadIdx.x & 31;
    int q = blockIdx.x*8 + (threadIdx.x >> 5);
    const float4* rp = pos4 + (size_t)b*NN0;
    float4 qp = rp[q];
    float qx = qp.x, qy = qp.y, qz = qp.z, qq = qp.w;

    unsigned m1v = 0xffffffffu, m2v = 0xffffffffu, m3v = 0xffffffffu;
    int m1s = 0, m2s = 0, m3s = 0;
    #pragma unroll
    for (int i = 0; i < CNT; i++) {
        float4 r4 = rp[i*32 + lane];
        float dt = qx*r4.x + qy*r4.y + qz*r4.z;
        float dv = qq + r4.w - 2.0f*dt;
        unsigned u = ordf(dv);
        INS3(u, i);
    }
    size_t obase = ((size_t)b*Nq + q)*3;
    #pragma unroll
    for (int s = 0; s < 3; s++) {
        unsigned mh = __reduce_min_sync(0xffffffffu, m1v);
        unsigned cand = (m1v == mh) ? (unsigned)(m1s*32 + lane) : 0xffffffffu;
        unsigned ml = __reduce_min_sync(0xffffffffu, cand);
        if (lane == 0) {
            oidx[obase + s] = (int)ml;
            od2[obase + s]  = fmaxf(unordf(mh), 0.0f);
        }
        if (cand == ml && m1v == mh) {
            m1v = m2v; m1s = m2s;
            m2v = m3v; m2s = m3s;
            m3v = 0xffffffffu;
        }
    }
}

// ---------------- down: gather + 2-layer MLP + max over 16 neighbors (j-block=2) ----------------
template<int C_PREV, int C_HID>
__global__ void down_kernel(const float* __restrict__ xprev, const float* __restrict__ pos,
                            const int* __restrict__ idx,
                            const float* __restrict__ W1d, const float* __restrict__ b1,
                            const float* __restrict__ W2d, const float* __restrict__ b2,
                            float* __restrict__ xout, int Nq, int xbs) {
    constexpr int CIN = 3 + C_PREV;
    extern __shared__ float sm[];
    float* featT = sm;               // CIN*16
    float* hT    = sm + CIN*16;      // C_HID*16
    __shared__ int nbs[16];
    int b = blockIdx.y, q = blockIdx.x;
    if (threadIdx.x < 16) nbs[threadIdx.x] = idx[((size_t)b*Nq + q)*16 + threadIdx.x];
    __syncthreads();
    const float* rp = pos + (size_t)b*NN0*3;
    float cx = rp[3*q+0], cy = rp[3*q+1], cz = rp[3*q+2];
    const float* xp = xprev + (size_t)b*xbs;
    for (int e = threadIdx.x; e < 16*CIN; e += blockDim.x) {
        int d = e >> 4, k = e & 15;
        int nb = nbs[k];
        float v;
        if      (d == 0) v = rp[3*nb+0] - cx;
        else if (d == 1) v = rp[3*nb+1] - cy;
        else if (d == 2) v = rp[3*nb+2] - cz;
        else             v = xp[(size_t)nb*C_PREV + (d-3)];
        featT[d*16 + k] = v;
    }
    __syncthreads();
    int j0 = 2*threadIdx.x;
    u64 a0[8], a1[8];
    {
        float2 bb = *reinterpret_cast<const float2*>(&b1[j0]);
        u64 p0 = pack2(bb.x, bb.x), p1 = pack2(bb.y, bb.y);
        #pragma unroll
        for (int i = 0; i < 8; i++) { a0[i] = p0; a1[i] = p1; }
    }
    #pragma unroll 2
    for (int d = 0; d < CIN; d++) {
        ulonglong2 w = *reinterpret_cast<const ulonglong2*>(W1d + 2*(d*C_HID + j0));
        const ulonglong2* f = reinterpret_cast<const ulonglong2*>(featT + d*16);
        ulonglong2 f0 = f[0], f1 = f[1], f2 = f[2], f3 = f[3];
        a0[0]=ffma2(f0.x,w.x,a0[0]); a0[1]=ffma2(f0.y,w.x,a0[1]);
        a0[2]=ffma2(f1.x,w.x,a0[2]); a0[3]=ffma2(f1.y,w.x,a0[3]);
        a0[4]=ffma2(f2.x,w.x,a0[4]); a0[5]=ffma2(f2.y,w.x,a0[5]);
        a0[6]=ffma2(f3.x,w.x,a0[6]); a0[7]=ffma2(f3.y,w.x,a0[7]);
        a1[0]=ffma2(f0.x,w.y,a1[0]); a1[1]=ffma2(f0.y,w.y,a1[1]);
        a1[2]=ffma2(f1.x,w.y,a1[2]); a1[3]=ffma2(f1.y,w.y,a1[3]);
        a1[4]=ffma2(f2.x,w.y,a1[4]); a1[5]=ffma2(f2.y,w.y,a1[5]);
        a1[6]=ffma2(f3.x,w.y,a1[6]); a1[7]=ffma2(f3.y,w.y,a1[7]);
    }
    {
        float4* h0 = reinterpret_cast<float4*>(hT + (size_t)j0*16);
        float4* h1 = reinterpret_cast<float4*>(hT + (size_t)(j0+1)*16);
        #pragma unroll
        for (int i = 0; i < 4; i++) {
            float2 x0 = unpack2(a0[2*i]), x1 = unpack2(a0[2*i+1]);
            h0[i] = make_float4(fmaxf(x0.x,0.f), fmaxf(x0.y,0.f), fmaxf(x1.x,0.f), fmaxf(x1.y,0.f));
            float2 y0 = unpack2(a1[2*i]), y1 = unpack2(a1[2*i+1]);
            h1[i] = make_float4(fmaxf(y0.x,0.f), fmaxf(y0.y,0.f), fmaxf(y1.x,0.f), fmaxf(y1.y,0.f));
        }
    }
    __syncthreads();
    {
        float2 bb = *reinterpret_cast<const float2*>(&b2[j0]);
        u64 p0 = pack2(bb.x, bb.x), p1 = pack2(bb.y, bb.y);
        #pragma unroll
        for (int i = 0; i < 8; i++) { a0[i] = p0; a1[i] = p1; }
    }
    #pragma unroll 2
    for (int d = 0; d < C_HID; d++) {
        ulonglong2 w = *reinterpret_cast<const ulonglong2*>(W2d + 2*(d*C_HID + j0));
        const ulonglong2* f = reinterpret_cast<const ulonglong2*>(hT + d*16);
        ulonglong2 f0 = f[0], f1 = f[1], f2 = f[2], f3 = f[3];
        a0[0]=ffma2(f0.x,w.x,a0[0]); a0[1]=ffma2(f0.y,w.x,a0[1]);
        a0[2]=ffma2(f1.x,w.x,a0[2]); a0[3]=ffma2(f1.y,w.x,a0[3]);
        a0[4]=ffma2(f2.x,w.x,a0[4]); a0[5]=ffma2(f2.y,w.x,a0[5]);
        a0[6]=ffma2(f3.x,w.x,a0[6]); a0[7]=ffma2(f3.y,w.x,a0[7]);
        a1[0]=ffma2(f0.x,w.y,a1[0]); a1[1]=ffma2(f0.y,w.y,a1[1]);
        a1[2]=ffma2(f1.x,w.y,a1[2]); a1[3]=ffma2(f1.y,w.y,a1[3]);
        a1[4]=ffma2(f2.x,w.y,a1[4]); a1[5]=ffma2(f2.y,w.y,a1[5]);
        a1[6]=ffma2(f3.x,w.y,a1[6]); a1[7]=ffma2(f3.y,w.y,a1[7]);
    }
    float m0 = -FLT_MAX, m1 = -FLT_MAX;
    #pragma unroll
    for (int i = 0; i < 8; i++) {
        float2 x = unpack2(a0[i]); m0 = fmaxf(m0, fmaxf(x.x, x.y));
        float2 y = unpack2(a1[i]); m1 = fmaxf(m1, fmaxf(y.x, y.y));
    }
    *reinterpret_cast<float2*>(&xout[((size_t)b*Nq + q)*C_HID + j0]) = make_float2(m0, m1);
}

// ---------------- up: 3-NN inverse-distance interp + cat + linear + relu ----------------
template<int C_XC, int C_PRV, int C_OUT>
__global__ void up_kernel(const float* __restrict__ xc, const float* __restrict__ prv,
                          const int* __restrict__ idx, const float* __restrict__ d2,
                          const float* __restrict__ Wd, const float* __restrict__ bias,
                          float* __restrict__ out, int Nq, int Nc) {
    constexpr int CIN = C_XC + C_PRV;
    constexpr int QT = 16;
    extern __shared__ float sm[];
    float* featT = sm;               // CIN * 16, [d][q]
    __shared__ float wsh[QT][3];
    __shared__ int   ish[QT][3];
    int b = blockIdx.y;
    int q0 = blockIdx.x * QT;
    if (threadIdx.x < QT) {
        int q = q0 + threadIdx.x;
        size_t base = ((size_t)b*Nq + q)*3;
        float w0 = 1.0f/(d2[base+0] + 1e-8f);
        float w1 = 1.0f/(d2[base+1] + 1e-8f);
        float w2 = 1.0f/(d2[base+2] + 1e-8f);
        float s = w0 + w1 + w2;
        wsh[threadIdx.x][0] = w0/s; wsh[threadIdx.x][1] = w1/s; wsh[threadIdx.x][2] = w2/s;
        ish[threadIdx.x][0] = idx[base+0]; ish[threadIdx.x][1] = idx[base+1]; ish[threadIdx.x][2] = idx[base+2];
    }
    __syncthreads();
    const float* xcb = xc + (size_t)b*Nc*C_XC;
    for (int e = threadIdx.x; e < CIN*QT; e += blockDim.x) {
        int d = e >> 4, qq = e & 15;
        float v;
        if (d < C_XC) {
            v = wsh[qq][0]*xcb[(size_t)ish[qq][0]*C_XC + d]
              + wsh[qq][1]*xcb[(size_t)ish[qq][1]*C_XC + d]
              + wsh[qq][2]*xcb[(size_t)ish[qq][2]*C_XC + d];
        } else {
            v = prv[((size_t)b*Nq + q0 + qq)*C_PRV + (d - C_XC)];
        }
        featT[e] = v;
    }
    __syncthreads();
    int j0 = 2*threadIdx.x;
    u64 a0[8], a1[8];
    {
        float2 bb = *reinterpret_cast<const float2*>(&bias[j0]);
        u64 p0 = pack2(bb.x, bb.x), p1 = pack2(bb.y, bb.y);
        #pragma unroll
        for (int i = 0; i < 8; i++) { a0[i] = p0; a1[i] = p1; }
    }
    #pragma unroll 2
    for (int d = 0; d < CIN; d++) {
        ulonglong2 w = *reinterpret_cast<const ulonglong2*>(Wd + 2*(d*C_OUT + j0));
        const ulonglong2* f = reinterpret_cast<const ulonglong2*>(featT + d*QT);
        ulonglong2 f0 = f[0], f1 = f[1], f2 = f[2], f3 = f[3];
        a0[0]=ffma2(f0.x,w.x,a0[0]); a0[1]=ffma2(f0.y,w.x,a0[1]);
        a0[2]=ffma2(f1.x,w.x,a0[2]); a0[3]=ffma2(f1.y,w.x,a0[3]);
        a0[4]=ffma2(f2.x,w.x,a0[4]); a0[5]=ffma2(f2.y,w.x,a0[5]);
        a0[6]=ffma2(f3.x,w.x,a0[6]); a0[7]=ffma2(f3.y,w.x,a0[7]);
        a1[0]=ffma2(f0.x,w.y,a1[0]); a1[1]=ffma2(f0.y,w.y,a1[1]);
        a1[2]=ffma2(f1.x,w.y,a1[2]); a1[3]=ffma2(f1.y,w.y,a1[3]);
        a1[4]=ffma2(f2.x,w.y,a1[4]); a1[5]=ffma2(f2.y,w.y,a1[5]);
        a1[6]=ffma2(f3.x,w.y,a1[6]); a1[7]=ffma2(f3.y,w.y,a1[7]);
    }
    size_t obase = ((size_t)b*Nq + q0)*C_OUT + j0;
    #pragma unroll
    for (int i = 0; i < 8; i++) {
        float2 x = unpack2(a0[i]), y = unpack2(a1[i]);
        *reinterpret_cast<float2*>(&out[obase + (size_t)(2*i+0)*C_OUT]) =
            make_float2(fmaxf(x.x,0.f), fmaxf(y.x,0.f));
        *reinterpret_cast<float2*>(&out[obase + (size_t)(2*i+1)*C_OUT]) =
            make_float2(fmaxf(x.y,0.f), fmaxf(y.y,0.f));
    }
}

// ---------------- fused: up2 + final MLP ----------------
__global__ void up2_final_kernel(const float* __restrict__ up1,
                                 const float* __restrict__ x0, const float* __restrict__ pos0,
                                 const int* __restrict__ idx, const float* __restrict__ d2,
                                 const float* __restrict__ u2Wd, const float* __restrict__ u2b,
                                 const float* __restrict__ fW1d, const float* __restrict__ fb1,
                                 const float* __restrict__ fW2d, const float* __restrict__ fb2,
                                 float* __restrict__ out) {
    constexpr int QT = 16;
    __shared__ float featT[134*QT];
    __shared__ float h1T[128*QT];
    __shared__ float wsh[QT][3];
    __shared__ int   ish[QT][3];
    int b = blockIdx.y;
    int q0 = blockIdx.x * QT;
    if (threadIdx.x < QT) {
        int q = q0 + threadIdx.x;
        size_t base = ((size_t)b*NN0 + q)*3;
        float w0 = 1.0f/(d2[base+0] + 1e-8f);
        float w1 = 1.0f/(d2[base+1] + 1e-8f);
        float w2 = 1.0f/(d2[base+2] + 1e-8f);
        float s = w0 + w1 + w2;
        wsh[threadIdx.x][0] = w0/s; wsh[threadIdx.x][1] = w1/s; wsh[threadIdx.x][2] = w2/s;
        ish[threadIdx.x][0] = idx[base+0]; ish[threadIdx.x][1] = idx[base+1]; ish[threadIdx.x][2] = idx[base+2];
    }
    __syncthreads();
    const float* xcb = up1 + (size_t)b*NN1*128;
    for (int e = threadIdx.x; e < 134*QT; e += 64) {
        int d = e >> 4, qq = e & 15;
        float v;
        if (d < 128) {
            v = wsh[qq][0]*xcb[(size_t)ish[qq][0]*128 + d]
              + wsh[qq][1]*xcb[(size_t)ish[qq][1]*128 + d]
              + wsh[qq][2]*xcb[(size_t)ish[qq][2]*128 + d];
        } else if (d < 131) {
            v = x0  [((size_t)b*NN0 + q0 + qq)*3 + (d-128)];
        } else {
            v = pos0[((size_t)b*NN0 + q0 + qq)*3 + (d-131)];
        }
        featT[e] = v;
    }
    __syncthreads();
    int j0 = 2*threadIdx.x;
    u64 a0[8], a1[8];

    // ---- stage u2: 134 -> 128, relu ----
    {
        float2 bb = *reinterpret_cast<const float2*>(&u2b[j0]);
        u64 p0 = pack2(bb.x, bb.x), p1 = pack2(bb.y, bb.y);
        #pragma unroll
        for (int i = 0; i < 8; i++) { a0[i] = p0; a1[i] = p1; }
    }
    #pragma unroll 2
    for (int d = 0; d < 134; d++) {
        ulonglong2 w = *reinterpret_cast<const ulonglong2*>(u2Wd + 2*(d*128 + j0));
        const ulonglong2* f = reinterpret_cast<const ulonglong2*>(featT + d*QT);
        ulonglong2 f0 = f[0], f1 = f[1], f2 = f[2], f3 = f[3];
        a0[0]=ffma2(f0.x,w.x,a0[0]); a0[1]=ffma2(f0.y,w.x,a0[1]);
        a0[2]=ffma2(f1.x,w.x,a0[2]); a0[3]=ffma2(f1.y,w.x,a0[3]);
        a0[4]=ffma2(f2.x,w.x,a0[4]); a0[5]=ffma2(f2.y,w.x,a0[5]);
        a0[6]=ffma2(f3.x,w.x,a0[6]); a0[7]=ffma2(f3.y,w.x,a0[7]);
        a1[0]=ffma2(f0.x,w.y,a1[0]); a1[1]=ffma2(f0.y,w.y,a1[1]);
        a1[2]=ffma2(f1.x,w.y,a1[2]); a1[3]=ffma2(f1.y,w.y,a1[3]);
        a1[4]=ffma2(f2.x,w.y,a1[4]); a1[5]=ffma2(f2.y,w.y,a1[5]);
        a1[6]=ffma2(f3.x,w.y,a1[6]); a1[7]=ffma2(f3.y,w.y,a1[7]);
    }
    {
        float4* h0 = reinterpret_cast<float4*>(h1T + (size_t)j0*QT);
        float4* h1 = reinterpret_cast<float4*>(h1T + (size_t)(j0+1)*QT);
        #pragma unroll
        for (int i = 0; i < 4; i++) {
            float2 x0v = unpack2(a0[2*i]), x1v = unpack2(a0[2*i+1]);
            h0[i] = make_float4(fmaxf(x0v.x,0.f), fmaxf(x0v.y,0.f), fmaxf(x1v.x,0.f), fmaxf(x1v.y,0.f));
            float2 y0v = unpack2(a1[2*i]), y1v = unpack2(a1[2*i+1]);
            h1[i] = make_float4(fmaxf(y0v.x,0.f), fmaxf(y0v.y,0.f), fmaxf(y1v.x,0.f), fmaxf(y1v.y,0.f));
        }
    }
    __syncthreads();

    // ---- stage f1: 128 -> 128, relu (into featT) ----
    {
        float2 bb = *reinterpret_cast<const float2*>(&fb1[j0]);
        u64 p0 = pack2(bb.x, bb.x), p1 = pack2(bb.y, bb.y);
        #pragma unroll
        for (int i = 0; i < 8; i++) { a0[i] = p0; a1[i] = p1; }
    }
    #pragma unroll 2
    for (int d = 0; d < 128; d++) {
        ulonglong2 w = *reinterpret_cast<const ulonglong2*>(fW1d + 2*(d*128 + j0));
        const ulonglong2* f = reinterpret_cast<const ulonglong2*>(h1T + d*QT);
        ulonglong2 f0 = f[0], f1 = f[1], f2 = f[2], f3 = f[3];
        a0[0]=ffma2(f0.x,w.x,a0[0]); a0[1]=ffma2(f0.y,w.x,a0[1]);
        a0[2]=ffma2(f1.x,w.x,a0[2]); a0[3]=ffma2(f1.y,w.x,a0[3]);
        a0[4]=ffma2(f2.x,w.x,a0[4]); a0[5]=ffma2(f2.y,w.x,a0[5]);
        a0[6]=ffma2(f3.x,w.x,a0[6]); a0[7]=ffma2(f3.y,w.x,a0[7]);
        a1[0]=ffma2(f0.x,w.y,a1[0]); a1[1]=ffma2(f0.y,w.y,a1[1]);
        a1[2]=ffma2(f1.x,w.y,a1[2]); a1[3]=ffma2(f1.y,w.y,a1[3]);
        a1[4]=ffma2(f2.x,w.y,a1[4]); a1[5]=ffma2(f2.y,w.y,a1[5]);
        a1[6]=ffma2(f3.x,w.y,a1[6]); a1[7]=ffma2(f3.y,w.y,a1[7]);
    }
    __syncthreads();
    {
        float4* h0 = reinterpret_cast<float4*>(featT + (size_t)j0*QT);
        float4* h1 = reinterpret_cast<float4*>(featT + (size_t)(j0+1)*QT);
        #pragma unroll
        for (int i = 0; i < 4; i++) {
            float2 x0v = unpack2(a0[2*i]), x1v = unpack2(a0[2*i+1]);
            h0[i] = make_float4(fmaxf(x0v.x,0.f), fmaxf(x0v.y,0.f), fmaxf(x1v.x,0.f), fmaxf(x1v.y,0.f));
            float2 y0v = unpack2(a1[2*i]), y1v = unpack2(a1[2*i+1]);
            h1[i] = make_float4(fmaxf(y0v.x,0.f), fmaxf(y0v.y,0.f), fmaxf(y1v.x,0.f), fmaxf(y1v.y,0.f));
        }
    }
    __syncthreads();

    // ---- stage f2: 128 -> 128, no relu ----
    {
        float2 bb = *reinterpret_cast<const float2*>(&fb2[j0]);
        u64 p0 = pack2(bb.x, bb.x), p1 = pack2(bb.y, bb.y);
        #pragma unroll
        for (int i = 0; i < 8; i++) { a0[i] = p0; a1[i] = p1; }
    }
    #pragma unroll 2
    for (int d = 0; d < 128; d++) {
        ulonglong2 w = *reinterpret_cast<const ulonglong2*>(fW2d + 2*(d*128 + j0));
        const ulonglong2* f = reinterpret_cast<const ulonglong2*>(featT + d*QT);
        ulonglong2 f0 = f[0], f1 = f[1], f2 = f[2], f3 = f[3];
        a0[0]=ffma2(f0.x,w.x,a0[0]); a0[1]=ffma2(f0.y,w.x,a0[1]);
        a0[2]=ffma2(f1.x,w.x,a0[2]); a0[3]=ffma2(f1.y,w.x,a0[3]);
        a0[4]=ffma2(f2.x,w.x,a0[4]); a0[5]=ffma2(f2.y,w.x,a0[5]);
        a0[6]=ffma2(f3.x,w.x,a0[6]); a0[7]=ffma2(f3.y,w.x,a0[7]);
        a1[0]=ffma2(f0.x,w.y,a1[0]); a1[1]=ffma2(f0.y,w.y,a1[1]);
        a1[2]=ffma2(f1.x,w.y,a1[2]); a1[3]=ffma2(f1.y,w.y,a1[3]);
        a1[4]=ffma2(f2.x,w.y,a1[4]); a1[5]=ffma2(f2.y,w.y,a1[5]);
        a1[6]=ffma2(f3.x,w.y,a1[6]); a1[7]=ffma2(f3.y,w.y,a1[7]);
    }
    size_t obase = ((size_t)b*NN0 + q0)*128 + j0;
    #pragma unroll
    for (int i = 0; i < 8; i++) {
        float2 x = unpack2(a0[i]), y = unpack2(a1[i]);
        *reinterpret_cast<float2*>(&out[obase + (size_t)(2*i+0)*128]) = make_float2(x.x, y.x);
        *reinterpret_cast<float2*>(&out[obase + (size_t)(2*i+1)*128]) = make_float2(x.y, y.y);
    }
}

// ---------------- host launch ----------------
extern "C" void kernel_launch(void* const* d_in, const int* in_sizes, int n_in,
                              void* d_out, int out_size) {
    const float* x    = (const float*)d_in[0];
    const float* pos  = (const float*)d_in[1];
    const float* d0W1 = (const float*)d_in[2];
    const float* d0b1 = (const float*)d_in[3];
    const float* d0W2 = (const float*)d_in[4];
    const float* d0b2 = (const float*)d_in[5];
    const float* d1W1 = (const float*)d_in[6];
    const float* d1b1 = (const float*)d_in[7];
    const float* d1W2 = (const float*)d_in[8];
    const float* d1b2 = (const float*)d_in[9];
    const float* d2W1 = (const float*)d_in[10];
    const float* d2b1 = (const float*)d_in[11];
    const float* d2W2 = (const float*)d_in[12];
    const float* d2b2 = (const float*)d_in[13];
    const float* u0W  = (const float*)d_in[14];
    const float* u0b  = (const float*)d_in[15];
    const float* u1W  = (const float*)d_in[16];
    const float* u1b  = (const float*)d_in[17];
    const float* u2W  = (const float*)d_in[18];
    const float* u2b  = (const float*)d_in[19];
    const float* fW1  = (const float*)d_in[20];
    const float* fb1  = (const float*)d_in[21];
    const float* fW2  = (const float*)d_in[22];
    const float* fb2  = (const float*)d_in[23];
    float* out = (float*)d_out;

    int *idx0, *idx1, *idx2, *uidx0, *uidx1, *uidx2;
    float *ud20, *ud21, *ud22, *x1, *x2, *x3, *up0, *up1, *wd;
    float4* pos4;
    cudaGetSymbolAddress((void**)&idx0,  g_idx0);
    cudaGetSymbolAddress((void**)&idx1,  g_idx1);
    cudaGetSymbolAddress((void**)&idx2,  g_idx2);
    cudaGetSymbolAddress((void**)&uidx0, g_uidx0);
    cudaGetSymbolAddress((void**)&uidx1, g_uidx1);
    cudaGetSymbolAddress((void**)&uidx2, g_uidx2);
    cudaGetSymbolAddress((void**)&ud20,  g_ud20);
    cudaGetSymbolAddress((void**)&ud21,  g_ud21);
    cudaGetSymbolAddress((void**)&ud22,  g_ud22);
    cudaGetSymbolAddress((void**)&x1,    g_x1);
    cudaGetSymbolAddress((void**)&x2,    g_x2);
    cudaGetSymbolAddress((void**)&x3,    g_x3);
    cudaGetSymbolAddress((void**)&up0,   g_up0);
    cudaGetSymbolAddress((void**)&up1,   g_up1);
    cudaGetSymbolAddress((void**)&wd,    g_wdup);
    cudaGetSymbolAddress((void**)&pos4,  g_pos4);

    const float* d0W1d = wd + 2*OFF_D0W1;
    const float* d0W2d = wd + 2*OFF_D0W2;
    const float* d1W1d = wd + 2*OFF_D1W1;
    const float* d1W2d = wd + 2*OFF_D1W2;
    const float* d2W1d = wd + 2*OFF_D2W1;
    const float* d2W2d = wd + 2*OFF_D2W2;
    const float* u0Wd  = wd + 2*OFF_U0W;
    const float* u1Wd  = wd + 2*OFF_U1W;
    const float* u2Wd  = wd + 2*OFF_U2W;
    const float* fW1d  = wd + 2*OFF_FW1;
    const float* fW2d  = wd + 2*OFF_FW2;

    cudaFuncSetAttribute((const void*)down_kernel<256,512>,
                         cudaFuncAttributeMaxDynamicSharedMemorySize, 56*1024);
    cudaFuncSetAttribute((const void*)up_kernel<512,256,256>,
                         cudaFuncAttributeMaxDynamicSharedMemorySize, 50*1024);

    // ---- preps ----
    prep_pos4_kernel<<<(Bz*NN0)/256, 256>>>(pos, pos4);
    dup_weights_kernel<<<(W_TOTAL+255)/256, 256>>>(
        d0W1,d0W2,d1W1,d1W2,d2W1,d2W2,u0W,u1W,u2W,fW1,fW2, wd);

    // ---- down 0: knn(2048 q, 8192 refs) + MLP ----
    knn16_kernel<32,8><<<dim3(NN1,Bz), 256>>>(pos4, NN1, idx0);
    down_kernel<3,128><<<dim3(NN1,Bz), 64, (6*16 + 128*16)*sizeof(float)>>>(
        x, pos, idx0, d0W1d,d0b1, d0W2d,d0b2, x1, NN1, NN0*3);
    // ---- down 1: knn(512 q, 2048 refs) + MLP ----
    knn16_kernel<8,8><<<dim3(NN2,Bz), 256>>>(pos4, NN2, idx1);
    down_kernel<128,256><<<dim3(NN2,Bz), 128, (131*16 + 256*16)*sizeof(float)>>>(
        x1, pos, idx1, d1W1d,d1b1, d1W2d,d1b2, x2, NN2, NN1*128);
    // ---- down 2: knn(128 q, 512 refs) + MLP ----
    knn16_kernel<2,8><<<dim3(NN3,Bz), 256>>>(pos4, NN3, idx2);
    down_kernel<256,512><<<dim3(NN3,Bz), 256, (259*16 + 512*16)*sizeof(float)>>>(
        x2, pos, idx2, d2W1d,d2b1, d2W2d,d2b2, x3, NN3, NN2*256);
    // ---- up 0: knn(512 q, 128 refs) + interp/MLP ----
    knn3_kernel<4><<<dim3(NN2/8,Bz), 256>>>(pos4, NN2, uidx0, ud20);
    up_kernel<512,256,256><<<dim3(NN2/16,Bz), 128, 768*16*sizeof(float)>>>(
        x3, x2, uidx0, ud20, u0Wd, u0b, up0, NN2, NN3);
    // ---- up 1: knn(2048 q, 512 refs) + interp/MLP ----
    knn3_kernel<16><<<dim3(NN1/8,Bz), 256>>>(pos4, NN1, uidx1, ud21);
    up_kernel<256,128,128><<<dim3(NN1/16,Bz), 64, 384*16*sizeof(float)>>>(
        up0, x1, uidx1, ud21, u1Wd, u1b, up1, NN1, NN2);
    // ---- up 2 + final MLP: knn(8192 q, 2048 refs) + fused ----
    knn3b_kernel<8,8><<<dim3(NN0,Bz), 256>>>(pos4, NN0, uidx2, ud22);
    up2_final_kernel<<<dim3(NN0/16,Bz), 64>>>(up1, x, pos, uidx2, ud22,
                                              u2Wd,u2b, fW1d,fb1, fW2d,fb2, out);
    // ---- second tuple element: pos0 passthrough ----
    if (out_size >= Bz*NN0*128 + Bz*NN0*3) {
        cudaMemcpyAsync(out + (size_t)Bz*NN0*128, pos,
                        (size_t)Bz*NN0*3*sizeof(float), cudaMemcpyDeviceToDevice);
    }
}